// round 1
// baseline (speedup 1.0000x reference)
#include <cuda_runtime.h>
#include <math.h>
#include <stdint.h>

// Problem constants
#define B_   8
#define N_   1024
#define F_   256      // F_IN
#define O_   256      // OUT
#define H_   2
#define D_   4
#define ROWS (B_ * N_)   // 8192

// ---------------- scratch (device globals; no allocations allowed) ----------------
__device__ float g_Wsum[D_ * F_ * O_];            // [d][f][o]  1 MB
__device__ float g_vsrc[D_ * F_];                 // [d][f]
__device__ float g_vdst[D_ * F_];
__device__ float g_Whsum[ROWS * D_ * O_];         // [(b*N+j)][d][o] interleaved, 32 MB
__device__ float g_esrc[D_ * B_ * N_];            // [d][b][i]
__device__ float g_edst[D_ * B_ * N_];            // [d][b][j]
__device__ uint8_t g_bits[N_ * N_];               // bit d set if A_d[i][j] != 0

// ---------------- prep: Wsum[d] = W[d,0]+W[d,1];  v = W[d,1] @ a[d,1] -------------
__global__ void prep_kernel(const float* __restrict__ W, const float* __restrict__ a) {
    int d = blockIdx.x;
    int tid = threadIdx.x;
    __shared__ float sa[2 * O_];
    for (int idx = tid; idx < 2 * O_; idx += blockDim.x)
        sa[idx] = a[(d * 2 + 1) * (2 * O_) + idx];
    __syncthreads();

    const float* W0 = W + (size_t)(d * 2 + 0) * F_ * O_;
    const float* W1 = W + (size_t)(d * 2 + 1) * F_ * O_;
    for (int idx = tid; idx < F_ * O_; idx += blockDim.x)
        g_Wsum[d * F_ * O_ + idx] = W0[idx] + W1[idx];

    // each thread owns one f (blockDim = 256 = F_)
    int f = tid;
    float s1 = 0.f, s2 = 0.f;
    const float* w1r = W1 + f * O_;
    for (int o = 0; o < O_; o++) {
        float w = w1r[o];
        s1 += w * sa[o];
        s2 += w * sa[O_ + o];
    }
    g_vsrc[d * F_ + f] = s1;
    g_vdst[d * F_ + f] = s2;
}

// ---------------- pack adjacency bits -------------------------------------------
__global__ void bits_kernel(const int* __restrict__ AU, const int* __restrict__ AD,
                            const int* __restrict__ AR, const int* __restrict__ AL) {
    int idx = blockIdx.x * blockDim.x + threadIdx.x;
    if (idx < N_ * N_) {
        uint8_t b = 0;
        if (AU[idx] != 0) b |= 1;
        if (AD[idx] != 0) b |= 2;
        if (AR[idx] != 0) b |= 4;
        if (AL[idx] != 0) b |= 8;
        g_bits[idx] = b;
    }
}

// ---------------- GEMM: Whsum[(row)][d][o] = X[row,:] @ Wsum[d] ------------------
// Tile 64x64, K-chunk 32, 256 threads, 4x4 micro-tile per thread.
__global__ void gemm_whsum_kernel(const float* __restrict__ X) {
    const int m0 = blockIdx.x * 64;
    const int n0 = blockIdx.y * 64;
    const int d  = blockIdx.z;
    const int tid = threadIdx.x;
    const int tx = tid & 15, ty = tid >> 4;

    __shared__ float As[32][68];   // [k][m], padded
    __shared__ float Bs[32][64];   // [k][n]

    float c[4][4];
#pragma unroll
    for (int i = 0; i < 4; i++)
#pragma unroll
        for (int j = 0; j < 4; j++) c[i][j] = 0.f;

    const float* Bbase = g_Wsum + d * F_ * O_;

    for (int k0 = 0; k0 < F_; k0 += 32) {
#pragma unroll
        for (int r = 0; r < 8; r++) {
            int idx = tid + r * 256;
            int m = idx >> 5, k = idx & 31;
            As[k][m] = X[(size_t)(m0 + m) * F_ + k0 + k];
        }
#pragma unroll
        for (int r = 0; r < 8; r++) {
            int idx = tid + r * 256;
            int k = idx >> 6, n = idx & 63;
            Bs[k][n] = Bbase[(size_t)(k0 + k) * O_ + n0 + n];
        }
        __syncthreads();
#pragma unroll
        for (int kk = 0; kk < 32; kk++) {
            float av[4], bv[4];
#pragma unroll
            for (int i = 0; i < 4; i++) av[i] = As[kk][ty * 4 + i];
#pragma unroll
            for (int j = 0; j < 4; j++) bv[j] = Bs[kk][tx * 4 + j];
#pragma unroll
            for (int i = 0; i < 4; i++)
#pragma unroll
                for (int j = 0; j < 4; j++) c[i][j] += av[i] * bv[j];
        }
        __syncthreads();
    }
#pragma unroll
    for (int i = 0; i < 4; i++) {
        int row = m0 + ty * 4 + i;
#pragma unroll
        for (int j = 0; j < 4; j++) {
            int col = n0 + tx * 4 + j;
            g_Whsum[((size_t)row * D_ + d) * O_ + col] = c[i][j];
        }
    }
}

// ---------------- e_src / e_dst: 8 dots of x rows with v vectors -----------------
__global__ void evec_kernel(const float* __restrict__ X) {
    int tid = threadIdx.x;
    int w = tid >> 5, lane = tid & 31;
    int row = blockIdx.x * 8 + w;                 // 0..8191
    if (row >= ROWS) return;
    int b = row >> 10, n = row & (N_ - 1);

    float xv[8];
#pragma unroll
    for (int t = 0; t < 8; t++) xv[t] = X[(size_t)row * F_ + lane + t * 32];

#pragma unroll
    for (int d = 0; d < D_; d++) {
        float s1 = 0.f, s2 = 0.f;
#pragma unroll
        for (int t = 0; t < 8; t++) {
            s1 += xv[t] * g_vsrc[d * F_ + lane + t * 32];
            s2 += xv[t] * g_vdst[d * F_ + lane + t * 32];
        }
#pragma unroll
        for (int off = 16; off > 0; off >>= 1) {
            s1 += __shfl_down_sync(0xffffffffu, s1, off);
            s2 += __shfl_down_sync(0xffffffffu, s2, off);
        }
        if (lane == 0) {
            g_esrc[(d * B_ + b) * N_ + n] = s1;
            g_edst[(d * B_ + b) * N_ + n] = s2;
        }
    }
}

// ---------------- main: softmax rows + masked accumulation -----------------------
// block: (b, i-tile of TI=4 rows), 256 threads (one per output channel o)
#define TI 4
__global__ void __launch_bounds__(256) main_kernel(float* __restrict__ out) {
    const int b  = blockIdx.x;
    const int i0 = blockIdx.y * TI;
    const int tid = threadIdx.x;

    __shared__ float  sh_e[TI][N_];      // e_total, then unnormalized exp
    __shared__ uint8_t sh_bits[TI][N_];
    __shared__ float  red[256];
    __shared__ float  sh_scale[TI];

    for (int idx = tid; idx < TI * N_; idx += 256) {
        int ii = idx >> 10, j = idx & (N_ - 1);
        sh_bits[ii][j] = g_bits[(size_t)(i0 + ii) * N_ + j];
    }
    __syncthreads();

    for (int ii = 0; ii < TI; ii++) {
        const int i = i0 + ii;
        float es[D_];
#pragma unroll
        for (int d = 0; d < D_; d++) es[d] = g_esrc[(d * B_ + b) * N_ + i];

        float pmax = -INFINITY;
        for (int j = tid; j < N_; j += 256) {
            int bits = sh_bits[ii][j];
            float e;
            if (bits) {
                int ds = 31 - __clz(bits);
                float s = es[ds] + g_edst[(ds * B_ + b) * N_ + j];
                e = s > 0.f ? s : 0.01f * s;
            } else {
                e = -INFINITY;
            }
            sh_e[ii][j] = e;
            pmax = fmaxf(pmax, e);
        }
        red[tid] = pmax; __syncthreads();
        for (int s = 128; s > 0; s >>= 1) {
            if (tid < s) red[tid] = fmaxf(red[tid], red[tid + s]);
            __syncthreads();
        }
        float rmax = red[0]; __syncthreads();

        float psum = 0.f;
        for (int j = tid; j < N_; j += 256) {
            float e = sh_e[ii][j];
            float wv = expf(e - rmax);      // exp(-inf - finite) = 0
            sh_e[ii][j] = wv;
            psum += wv;
        }
        red[tid] = psum; __syncthreads();
        for (int s = 128; s > 0; s >>= 1) {
            if (tid < s) red[tid] += red[tid + s];
            __syncthreads();
        }
        if (tid == 0) sh_scale[ii] = 1.0f / (red[0] * (float)H_);
        __syncthreads();
    }

    // accumulation: thread tid owns output channel o = tid for all TI rows
    float acc[TI];
#pragma unroll
    for (int ii = 0; ii < TI; ii++) acc[ii] = 0.f;

    const float* base = g_Whsum + ((size_t)b * N_) * D_ * O_ + tid;
    for (int j = 0; j < N_; j++) {
        int u = sh_bits[0][j] | sh_bits[1][j] | sh_bits[2][j] | sh_bits[3][j];
        if (!u) continue;
        const float* p = base + (size_t)j * D_ * O_;
        float v0 = 0.f, v1 = 0.f, v2 = 0.f, v3 = 0.f;
        if (u & 1) v0 = p[0 * O_];
        if (u & 2) v1 = p[1 * O_];
        if (u & 4) v2 = p[2 * O_];
        if (u & 8) v3 = p[3 * O_];
#pragma unroll
        for (int ii = 0; ii < TI; ii++) {
            int bits = sh_bits[ii][j];
            if (!bits) continue;
            float wv = sh_e[ii][j];
            if (bits & 1) acc[ii] += wv * v0;
            if (bits & 2) acc[ii] += wv * v1;
            if (bits & 4) acc[ii] += wv * v2;
            if (bits & 8) acc[ii] += wv * v3;
        }
    }
#pragma unroll
    for (int ii = 0; ii < TI; ii++)
        out[((size_t)(b * N_ + i0 + ii)) * O_ + tid] = acc[ii] * sh_scale[ii];
}

// ---------------- launch ---------------------------------------------------------
extern "C" void kernel_launch(void* const* d_in, const int* in_sizes, int n_in,
                              void* d_out, int out_size) {
    const float* x  = (const float*)d_in[0];
    const int*   AU = (const int*)d_in[1];
    const int*   AD = (const int*)d_in[2];
    const int*   AR = (const int*)d_in[3];
    const int*   AL = (const int*)d_in[4];
    const float* W  = (const float*)d_in[5];
    const float* a  = (const float*)d_in[6];
    float* out = (float*)d_out;

    prep_kernel<<<D_, 256>>>(W, a);
    bits_kernel<<<(N_ * N_) / 256, 256>>>(AU, AD, AR, AL);
    gemm_whsum_kernel<<<dim3(ROWS / 64, O_ / 64, D_), 256>>>(x);
    evec_kernel<<<ROWS / 8, 256>>>(x);
    main_kernel<<<dim3(B_, N_ / TI), 256>>>(out);
}

// round 2
// speedup vs baseline: 1.0865x; 1.0865x over previous
#include <cuda_runtime.h>
#include <math.h>
#include <stdint.h>

// Problem constants
#define B_   8
#define N_   1024
#define F_   256      // F_IN
#define O_   256      // OUT
#define H_   2
#define D_   4
#define ROWS (B_ * N_)   // 8192
#define TI   16          // i-rows per block in main kernel

// ---------------- scratch (device globals; no allocations allowed) ----------------
__device__ float g_Wsum[D_ * F_ * O_];            // [d][f][o]  1 MB
__device__ float g_vsrc[D_ * F_];                 // [d][f]
__device__ float g_vdst[D_ * F_];
__device__ float g_Whsum[ROWS * D_ * O_];         // [(b*N+j)][d][o] interleaved, 32 MB
__device__ float g_esrc[D_ * B_ * N_];            // [d][b][i]
__device__ float g_edst[D_ * B_ * N_];            // [d][b][j]
__device__ uint8_t g_bits[N_ * N_];               // bit d set if A_d[i][j] != 0

// packed f32x2 FMA (ptxas never emits FFMA2 from C++; PTX fma.rn.f32x2 only)
#define FMA2(d, a, b) asm("fma.rn.f32x2 %0, %1, %2, %0;" : "+l"(d) : "l"(a), "l"(b))

// ---------------- prep: Wsum[d] = W[d,0]+W[d,1];  v = W[d,1] @ a[d,1] -------------
__global__ void prep_kernel(const float* __restrict__ W, const float* __restrict__ a) {
    int d = blockIdx.x;
    int tid = threadIdx.x;
    __shared__ float sa[2 * O_];
    for (int idx = tid; idx < 2 * O_; idx += blockDim.x)
        sa[idx] = a[(d * 2 + 1) * (2 * O_) + idx];
    __syncthreads();

    const float* W0 = W + (size_t)(d * 2 + 0) * F_ * O_;
    const float* W1 = W + (size_t)(d * 2 + 1) * F_ * O_;
    for (int idx = tid; idx < F_ * O_; idx += blockDim.x)
        g_Wsum[d * F_ * O_ + idx] = W0[idx] + W1[idx];

    int f = tid;   // blockDim = 256 = F_
    float s1 = 0.f, s2 = 0.f;
    const float* w1r = W1 + f * O_;
    for (int o = 0; o < O_; o++) {
        float w = w1r[o];
        s1 += w * sa[o];
        s2 += w * sa[O_ + o];
    }
    g_vsrc[d * F_ + f] = s1;
    g_vdst[d * F_ + f] = s2;
}

// ---------------- pack adjacency bits -------------------------------------------
__global__ void bits_kernel(const int* __restrict__ AU, const int* __restrict__ AD,
                            const int* __restrict__ AR, const int* __restrict__ AL) {
    int idx = blockIdx.x * blockDim.x + threadIdx.x;
    if (idx < N_ * N_) {
        uint8_t b = 0;
        if (AU[idx] != 0) b |= 1;
        if (AD[idx] != 0) b |= 2;
        if (AR[idx] != 0) b |= 4;
        if (AL[idx] != 0) b |= 8;
        g_bits[idx] = b;
    }
}

// ---------------- GEMM: Whsum[(row)][d][o] = X[row,:] @ Wsum[d] ------------------
__global__ void gemm_whsum_kernel(const float* __restrict__ X) {
    const int m0 = blockIdx.x * 64;
    const int n0 = blockIdx.y * 64;
    const int d  = blockIdx.z;
    const int tid = threadIdx.x;
    const int tx = tid & 15, ty = tid >> 4;

    __shared__ float As[32][68];
    __shared__ float Bs[32][64];

    float c[4][4];
#pragma unroll
    for (int i = 0; i < 4; i++)
#pragma unroll
        for (int j = 0; j < 4; j++) c[i][j] = 0.f;

    const float* Bbase = g_Wsum + d * F_ * O_;

    for (int k0 = 0; k0 < F_; k0 += 32) {
#pragma unroll
        for (int r = 0; r < 8; r++) {
            int idx = tid + r * 256;
            int m = idx >> 5, k = idx & 31;
            As[k][m] = X[(size_t)(m0 + m) * F_ + k0 + k];
        }
#pragma unroll
        for (int r = 0; r < 8; r++) {
            int idx = tid + r * 256;
            int k = idx >> 6, n = idx & 63;
            Bs[k][n] = Bbase[(size_t)(k0 + k) * O_ + n0 + n];
        }
        __syncthreads();
#pragma unroll
        for (int kk = 0; kk < 32; kk++) {
            float av[4], bv[4];
#pragma unroll
            for (int i = 0; i < 4; i++) av[i] = As[kk][ty * 4 + i];
#pragma unroll
            for (int j = 0; j < 4; j++) bv[j] = Bs[kk][tx * 4 + j];
#pragma unroll
            for (int i = 0; i < 4; i++)
#pragma unroll
                for (int j = 0; j < 4; j++) c[i][j] += av[i] * bv[j];
        }
        __syncthreads();
    }
#pragma unroll
    for (int i = 0; i < 4; i++) {
        int row = m0 + ty * 4 + i;
#pragma unroll
        for (int j = 0; j < 4; j++) {
            int col = n0 + tx * 4 + j;
            g_Whsum[((size_t)row * D_ + d) * O_ + col] = c[i][j];
        }
    }
}

// ---------------- e_src / e_dst -------------------------------------------------
__global__ void evec_kernel(const float* __restrict__ X) {
    int tid = threadIdx.x;
    int w = tid >> 5, lane = tid & 31;
    int row = blockIdx.x * 8 + w;
    if (row >= ROWS) return;
    int b = row >> 10, n = row & (N_ - 1);

    float xv[8];
#pragma unroll
    for (int t = 0; t < 8; t++) xv[t] = X[(size_t)row * F_ + lane + t * 32];

#pragma unroll
    for (int d = 0; d < D_; d++) {
        float s1 = 0.f, s2 = 0.f;
#pragma unroll
        for (int t = 0; t < 8; t++) {
            s1 += xv[t] * g_vsrc[d * F_ + lane + t * 32];
            s2 += xv[t] * g_vdst[d * F_ + lane + t * 32];
        }
#pragma unroll
        for (int off = 16; off > 0; off >>= 1) {
            s1 += __shfl_down_sync(0xffffffffu, s1, off);
            s2 += __shfl_down_sync(0xffffffffu, s2, off);
        }
        if (lane == 0) {
            g_esrc[(d * B_ + b) * N_ + n] = s1;
            g_edst[(d * B_ + b) * N_ + n] = s2;
        }
    }
}

// ---------------- main: softmax + masked accumulation (TI=16, vec4, FFMA2) -------
// Dynamic smem layout:
//   float  eT[N_ * 20]        (wv transposed: eT[j*20 + ii]; stride 20 => 16B aligned)
//   float  edst_s[D_ * N_]
//   float  red[4 * O_]
//   float  scale[TI]
//   uint8  bitsT[N_ * 16]     (bitsT[j*16 + ii], uint4-loadable per j)
#define SM_ET    0
#define SM_EDST  (N_ * 20)
#define SM_RED   (SM_EDST + D_ * N_)
#define SM_SCALE (SM_RED + 4 * O_)
#define SM_F32   (SM_SCALE + TI)            // total floats
#define SM_BITS  (SM_F32 * 4)               // byte offset of bitsT
#define SM_TOTAL (SM_BITS + N_ * 16)        // total bytes

__global__ void __launch_bounds__(256) main_kernel(float* __restrict__ out) {
    extern __shared__ float smf[];
    float*   eT     = smf + SM_ET;
    float*   edst_s = smf + SM_EDST;
    float*   red    = smf + SM_RED;
    float*   scale  = smf + SM_SCALE;
    uint8_t* bitsT  = (uint8_t*)smf + SM_BITS;

    const int b   = blockIdx.x;
    const int i0  = blockIdx.y * TI;
    const int tid = threadIdx.x;
    const int w   = tid >> 5, lane = tid & 31;

    // ---- phase 0: stage edst planes + transposed bits ----
    for (int idx = tid; idx < D_ * N_; idx += 256)
        edst_s[idx] = g_edst[((idx >> 10) * B_ + b) * N_ + (idx & (N_ - 1))];
    for (int idx = tid; idx < TI * N_; idx += 256) {
        int ii = idx >> 10, j = idx & (N_ - 1);
        bitsT[j * 16 + ii] = g_bits[(size_t)(i0 + ii) * N_ + j];
    }
    __syncthreads();

    // ---- phase 1: per-row softmax weights (warp w handles rows w, w+8) ----
    for (int rr = 0; rr < 2; rr++) {
        const int ii = w + rr * 8;
        const int i  = i0 + ii;
        float es[D_];
#pragma unroll
        for (int d = 0; d < D_; d++) es[d] = g_esrc[(d * B_ + b) * N_ + i];

        float pmax = -INFINITY;
        for (int j = lane; j < N_; j += 32) {
            int bits = bitsT[j * 16 + ii];
            float e;
            if (bits) {
                int ds = 31 - __clz(bits);
                float s = es[ds] + edst_s[ds * N_ + j];
                e = s > 0.f ? s : 0.01f * s;
            } else e = -INFINITY;
            eT[j * 20 + ii] = e;
            pmax = fmaxf(pmax, e);
        }
#pragma unroll
        for (int off = 16; off > 0; off >>= 1)
            pmax = fmaxf(pmax, __shfl_xor_sync(0xffffffffu, pmax, off));

        float psum = 0.f;
        for (int j = lane; j < N_; j += 32) {
            float wv = __expf(eT[j * 20 + ii] - pmax);   // exp(-inf)=0
            eT[j * 20 + ii] = wv;
            psum += wv;
        }
#pragma unroll
        for (int off = 16; off > 0; off >>= 1)
            psum += __shfl_xor_sync(0xffffffffu, psum, off);
        if (lane == 0) scale[ii] = 1.0f / (psum * (float)H_);
    }
    __syncthreads();

    // ---- phase 2: masked accumulation ----
    const int g = tid >> 6;                // j-group 0..3 (warp-uniform)
    const int c = (tid & 63) << 2;         // channel quad base

    unsigned long long acc[TI][2];
#pragma unroll
    for (int ii = 0; ii < TI; ii++) { acc[ii][0] = 0ull; acc[ii][1] = 0ull; }

    const float* base = g_Whsum + ((size_t)b * N_) * D_ * O_ + c;

#pragma unroll 2
    for (int j = g; j < N_; j += 4) {
        // 16 row-bits for this j (uniform across warp -> broadcast LDS.128)
        uint4 bw = *(const uint4*)(bitsT + j * 16);
        unsigned bwords[4] = {bw.x, bw.y, bw.z, bw.w};
        // 16 softmax weights (uniform broadcast)
        const float4* wp = (const float4*)(eT + j * 20);
        float4 w4[4] = {wp[0], wp[1], wp[2], wp[3]};
        float wvs[16];
#pragma unroll
        for (int q = 0; q < 4; q++) {
            wvs[q * 4 + 0] = ((const float*)&w4[q])[0];
            wvs[q * 4 + 1] = ((const float*)&w4[q])[1];
            wvs[q * 4 + 2] = ((const float*)&w4[q])[2];
            wvs[q * 4 + 3] = ((const float*)&w4[q])[3];
        }

        const float* p = base + (size_t)j * D_ * O_;
        ulonglong2 v0 = *(const ulonglong2*)(p);
        ulonglong2 v1 = *(const ulonglong2*)(p + O_);
        ulonglong2 v2 = *(const ulonglong2*)(p + 2 * O_);
        ulonglong2 v3 = *(const ulonglong2*)(p + 3 * O_);

#pragma unroll
        for (int ii = 0; ii < TI; ii++) {
            unsigned bbyte = (bwords[ii >> 2] >> ((ii & 3) * 8)) & 0xFF;
            if (!bbyte) continue;               // warp-uniform branch
            unsigned long long wvp;
            asm("mov.b64 %0, {%1, %1};" : "=l"(wvp) : "r"(__float_as_uint(wvs[ii])));
            if (bbyte & 1) { FMA2(acc[ii][0], wvp, v0.x); FMA2(acc[ii][1], wvp, v0.y); }
            if (bbyte & 2) { FMA2(acc[ii][0], wvp, v1.x); FMA2(acc[ii][1], wvp, v1.y); }
            if (bbyte & 4) { FMA2(acc[ii][0], wvp, v2.x); FMA2(acc[ii][1], wvp, v2.y); }
            if (bbyte & 8) { FMA2(acc[ii][0], wvp, v3.x); FMA2(acc[ii][1], wvp, v3.y); }
        }
    }

    // ---- phase 3: reduce across the 4 j-groups, write out ----
    for (int ii = 0; ii < TI; ii++) {
        float f0, f1, f2, f3;
        asm("mov.b64 {%0, %1}, %2;" : "=f"(f0), "=f"(f1) : "l"(acc[ii][0]));
        asm("mov.b64 {%0, %1}, %2;" : "=f"(f2), "=f"(f3) : "l"(acc[ii][1]));
        red[g * O_ + c + 0] = f0;
        red[g * O_ + c + 1] = f1;
        red[g * O_ + c + 2] = f2;
        red[g * O_ + c + 3] = f3;
        __syncthreads();
        float s = red[tid] + red[O_ + tid] + red[2 * O_ + tid] + red[3 * O_ + tid];
        out[((size_t)(b * N_ + i0 + ii)) * O_ + tid] = s * scale[ii];
        __syncthreads();
    }
}

// ---------------- launch ---------------------------------------------------------
extern "C" void kernel_launch(void* const* d_in, const int* in_sizes, int n_in,
                              void* d_out, int out_size) {
    const float* x  = (const float*)d_in[0];
    const int*   AU = (const int*)d_in[1];
    const int*   AD = (const int*)d_in[2];
    const int*   AR = (const int*)d_in[3];
    const int*   AL = (const int*)d_in[4];
    const float* W  = (const float*)d_in[5];
    const float* a  = (const float*)d_in[6];
    float* out = (float*)d_out;

    cudaFuncSetAttribute(main_kernel, cudaFuncAttributeMaxDynamicSharedMemorySize, SM_TOTAL);

    prep_kernel<<<D_, 256>>>(W, a);
    bits_kernel<<<(N_ * N_) / 256, 256>>>(AU, AD, AR, AL);
    gemm_whsum_kernel<<<dim3(ROWS / 64, O_ / 64, D_), 256>>>(x);
    evec_kernel<<<ROWS / 8, 256>>>(x);
    main_kernel<<<dim3(B_, N_ / TI), 256, SM_TOTAL>>>(out);
}

// round 4
// speedup vs baseline: 3.9791x; 3.6625x over previous
#include <cuda_runtime.h>
#include <cuda_fp16.h>
#include <math.h>
#include <stdint.h>

// Problem constants
#define B_   8
#define N_   1024
#define F_   256
#define O_   256
#define H_   2
#define D_   4
#define ROWS (B_ * N_)       // 8192
#define KTOT 4096            // D_ * N_

// ---------------- scratch ---------------------------------------------------------
__device__ float   g_Wsum[D_ * F_ * O_];
__device__ float   g_vsrc[D_ * F_];
__device__ float   g_vdst[D_ * F_];
__device__ float   g_esrc[D_ * B_ * N_];
__device__ float   g_edst[D_ * B_ * N_];
__device__ uint8_t g_bits[N_ * N_];
__device__ __half  g_P [ROWS * KTOT];           // [b*N+i][d*N+j]  67 MB
__device__ __half  g_Vt[B_ * O_ * KTOT];        // [b*O+o][d*N+j]  17 MB

__device__ __forceinline__ uint32_t smem_u32(const void* p) {
    uint32_t a;
    asm("{ .reg .u64 t; cvta.to.shared.u64 t, %1; cvt.u32.u64 %0, t; }" : "=r"(a) : "l"(p));
    return a;
}

#define LDSM_X4(r0, r1, r2, r3, addr) \
    asm volatile("ldmatrix.sync.aligned.m8n8.x4.shared.b16 {%0,%1,%2,%3}, [%4];" \
        : "=r"(r0), "=r"(r1), "=r"(r2), "=r"(r3) : "r"(addr))

#define MMA16816(c0, c1, c2, c3, a0, a1, a2, a3, b0, b1) \
    asm volatile("mma.sync.aligned.m16n8k16.row.col.f32.f16.f16.f32 " \
        "{%0,%1,%2,%3}, {%4,%5,%6,%7}, {%8,%9}, {%0,%1,%2,%3};" \
        : "+f"(c0), "+f"(c1), "+f"(c2), "+f"(c3) \
        : "r"(a0), "r"(a1), "r"(a2), "r"(a3), "r"(b0), "r"(b1))

// ---------------- prep ------------------------------------------------------------
__global__ void prep_kernel(const float* __restrict__ W, const float* __restrict__ a) {
    int d = blockIdx.x;
    int tid = threadIdx.x;
    __shared__ float sa[2 * O_];
    for (int idx = tid; idx < 2 * O_; idx += blockDim.x)
        sa[idx] = a[(d * 2 + 1) * (2 * O_) + idx];
    __syncthreads();

    const float* W0 = W + (size_t)(d * 2 + 0) * F_ * O_;
    const float* W1 = W + (size_t)(d * 2 + 1) * F_ * O_;
    for (int idx = tid; idx < F_ * O_; idx += blockDim.x)
        g_Wsum[d * F_ * O_ + idx] = W0[idx] + W1[idx];

    int f = tid;
    float s1 = 0.f, s2 = 0.f;
    const float* w1r = W1 + f * O_;
    for (int o = 0; o < O_; o++) {
        float w = w1r[o];
        s1 += w * sa[o];
        s2 += w * sa[O_ + o];
    }
    g_vsrc[d * F_ + f] = s1;
    g_vdst[d * F_ + f] = s2;
}

// ---------------- bits ------------------------------------------------------------
__global__ void bits_kernel(const int* __restrict__ AU, const int* __restrict__ AD,
                            const int* __restrict__ AR, const int* __restrict__ AL) {
    int idx = blockIdx.x * blockDim.x + threadIdx.x;
    if (idx < N_ * N_) {
        uint8_t b = 0;
        if (AU[idx] != 0) b |= 1;
        if (AD[idx] != 0) b |= 2;
        if (AR[idx] != 0) b |= 4;
        if (AL[idx] != 0) b |= 8;
        g_bits[idx] = b;
    }
}

// ---------------- GEMM: Vt[b][o][d*N+j] = fp16( X[b,j,:] @ Wsum[d][:,o] ) ---------
__global__ void gemm_whsum_kernel(const float* __restrict__ X) {
    const int m0 = blockIdx.x * 64;       // global row m = b*N + j
    const int n0 = blockIdx.y * 64;       // o
    const int d  = blockIdx.z;
    const int tid = threadIdx.x;
    const int tx = tid & 15, ty = tid >> 4;

    __shared__ float As[32][68];
    __shared__ float Bs[32][64];

    float c[4][4];
#pragma unroll
    for (int i = 0; i < 4; i++)
#pragma unroll
        for (int j = 0; j < 4; j++) c[i][j] = 0.f;

    const float* Bbase = g_Wsum + d * F_ * O_;

    for (int k0 = 0; k0 < F_; k0 += 32) {
#pragma unroll
        for (int r = 0; r < 8; r++) {
            int idx = tid + r * 256;
            int m = idx >> 5, k = idx & 31;
            As[k][m] = X[(size_t)(m0 + m) * F_ + k0 + k];
        }
#pragma unroll
        for (int r = 0; r < 8; r++) {
            int idx = tid + r * 256;
            int k = idx >> 6, n = idx & 63;
            Bs[k][n] = Bbase[(size_t)(k0 + k) * O_ + n0 + n];
        }
        __syncthreads();
#pragma unroll
        for (int kk = 0; kk < 32; kk++) {
            float av[4], bv[4];
#pragma unroll
            for (int i = 0; i < 4; i++) av[i] = As[kk][ty * 4 + i];
#pragma unroll
            for (int j = 0; j < 4; j++) bv[j] = Bs[kk][tx * 4 + j];
#pragma unroll
            for (int i = 0; i < 4; i++)
#pragma unroll
                for (int j = 0; j < 4; j++) c[i][j] += av[i] * bv[j];
        }
        __syncthreads();
    }

    // epilogue: write fp16, transposed into Vt[b][o][d*N + j]
    const int bb = m0 >> 10;
    const int j0 = (m0 & (N_ - 1)) + ty * 4;
#pragma unroll
    for (int jj = 0; jj < 4; jj++) {
        int col = n0 + tx * 4 + jj;
        uint16_t h0 = __half_as_ushort(__float2half_rn(c[0][jj]));
        uint16_t h1 = __half_as_ushort(__float2half_rn(c[1][jj]));
        uint16_t h2 = __half_as_ushort(__float2half_rn(c[2][jj]));
        uint16_t h3 = __half_as_ushort(__float2half_rn(c[3][jj]));
        uint64_t pack = (uint64_t)h0 | ((uint64_t)h1 << 16) | ((uint64_t)h2 << 32) | ((uint64_t)h3 << 48);
        *(uint64_t*)(g_Vt + ((size_t)(bb * O_ + col)) * KTOT + d * N_ + j0) = pack;
    }
}

// ---------------- e_src / e_dst ---------------------------------------------------
__global__ void evec_kernel(const float* __restrict__ X) {
    int tid = threadIdx.x;
    int w = tid >> 5, lane = tid & 31;
    int row = blockIdx.x * 8 + w;
    if (row >= ROWS) return;
    int b = row >> 10, n = row & (N_ - 1);

    float xv[8];
#pragma unroll
    for (int t = 0; t < 8; t++) xv[t] = X[(size_t)row * F_ + lane + t * 32];

#pragma unroll
    for (int d = 0; d < D_; d++) {
        float s1 = 0.f, s2 = 0.f;
#pragma unroll
        for (int t = 0; t < 8; t++) {
            s1 += xv[t] * g_vsrc[d * F_ + lane + t * 32];
            s2 += xv[t] * g_vdst[d * F_ + lane + t * 32];
        }
#pragma unroll
        for (int off = 16; off > 0; off >>= 1) {
            s1 += __shfl_down_sync(0xffffffffu, s1, off);
            s2 += __shfl_down_sync(0xffffffffu, s2, off);
        }
        if (lane == 0) {
            g_esrc[(d * B_ + b) * N_ + n] = s1;
            g_edst[(d * B_ + b) * N_ + n] = s2;
        }
    }
}

// ---------------- P build: softmax row -> fp16 P ----------------------------------
__global__ void __launch_bounds__(256) pbuild_kernel() {
    const int row = blockIdx.x;            // b*N + i
    const int b = row >> 10, i = row & (N_ - 1);
    const int tid = threadIdx.x;
    const int wid = tid >> 5, lane = tid & 31;
    const int j0 = tid * 4;

    __shared__ float red[8];
    __shared__ float bc[2];

    uint32_t bw = ((const uint32_t*)(g_bits + (size_t)i * N_))[tid];

    float es0 = g_esrc[(0 * B_ + b) * N_ + i];
    float es1 = g_esrc[(1 * B_ + b) * N_ + i];
    float es2 = g_esrc[(2 * B_ + b) * N_ + i];
    float es3 = g_esrc[(3 * B_ + b) * N_ + i];

    float4 ed0 = *(const float4*)(g_edst + (0 * B_ + b) * N_ + j0);
    float4 ed1 = *(const float4*)(g_edst + (1 * B_ + b) * N_ + j0);
    float4 ed2 = *(const float4*)(g_edst + (2 * B_ + b) * N_ + j0);
    float4 ed3 = *(const float4*)(g_edst + (3 * B_ + b) * N_ + j0);

    float e[4];
    unsigned byt[4];
#pragma unroll
    for (int q = 0; q < 4; q++) {
        unsigned bb8 = (bw >> (q * 8)) & 0xFF;
        byt[q] = bb8;
        float ev = -INFINITY;
        if (bb8) {
            int ds = 31 - __clz(bb8);
            float e0q = (q == 0) ? ed0.x : (q == 1) ? ed0.y : (q == 2) ? ed0.z : ed0.w;
            float e1q = (q == 0) ? ed1.x : (q == 1) ? ed1.y : (q == 2) ? ed1.z : ed1.w;
            float e2q = (q == 0) ? ed2.x : (q == 1) ? ed2.y : (q == 2) ? ed2.z : ed2.w;
            float e3q = (q == 0) ? ed3.x : (q == 1) ? ed3.y : (q == 2) ? ed3.z : ed3.w;
            float edv = (ds == 0) ? e0q : (ds == 1) ? e1q : (ds == 2) ? e2q : e3q;
            float esv = (ds == 0) ? es0 : (ds == 1) ? es1 : (ds == 2) ? es2 : es3;
            float s = esv + edv;
            ev = s > 0.f ? s : 0.01f * s;
        }
        e[q] = ev;
    }

    float m = fmaxf(fmaxf(e[0], e[1]), fmaxf(e[2], e[3]));
#pragma unroll
    for (int off = 16; off > 0; off >>= 1)
        m = fmaxf(m, __shfl_xor_sync(0xffffffffu, m, off));
    if (lane == 0) red[wid] = m;
    __syncthreads();
    if (tid == 0) {
        float mm = red[0];
#pragma unroll
        for (int k = 1; k < 8; k++) mm = fmaxf(mm, red[k]);
        bc[0] = mm;
    }
    __syncthreads();
    float rmax = bc[0];

    float wv[4], psum = 0.f;
#pragma unroll
    for (int q = 0; q < 4; q++) {
        wv[q] = __expf(e[q] - rmax);
        psum += wv[q];
    }
#pragma unroll
    for (int off = 16; off > 0; off >>= 1)
        psum += __shfl_xor_sync(0xffffffffu, psum, off);
    if (lane == 0) red[wid] = psum;
    __syncthreads();
    if (tid == 0) {
        float ss = 0.f;
#pragma unroll
        for (int k = 0; k < 8; k++) ss += red[k];
        bc[1] = 1.0f / (ss * (float)H_);
    }
    __syncthreads();
    float inv = bc[1];

    __half* Prow = g_P + (size_t)row * KTOT;
#pragma unroll
    for (int d = 0; d < D_; d++) {
        uint64_t pack = 0;
#pragma unroll
        for (int q = 0; q < 4; q++) {
            float v = (byt[q] >> d) & 1 ? wv[q] * inv : 0.f;
            pack |= (uint64_t)__half_as_ushort(__float2half_rn(v)) << (q * 16);
        }
        *(uint64_t*)(Prow + d * N_ + j0) = pack;
    }
}

// ---------------- main GEMM: out[b] = P[b] @ Vt[b]^T  via mma.sync (HMMA) ---------
// Block tile 128 (i) x 128 (o), K chunks of 64, double-buffered smem.
// Smem rows padded to stride 72 halves (144B) -> conflict-free ldmatrix.
#define STRD 72
#define ABUF (128 * STRD)                 // halves per matrix buffer
#define HSM_TOTAL (4 * ABUF * 2)          // bytes: 2 bufs x (A+B)

__global__ void __launch_bounds__(256, 1) maintc_kernel(float* __restrict__ out) {
    extern __shared__ __align__(16) __half hsm[];
    // layout: buf s: A at s*(2*ABUF), B at s*(2*ABUF)+ABUF
    const int tid = threadIdx.x;
    const int wid = tid >> 5, lane = tid & 31;
    const int m0 = blockIdx.x * 128;
    const int n0 = blockIdx.y * 128;
    const int b  = blockIdx.z;

    const int wm = wid & 3;          // warp row tile (32 rows)
    const int wn = wid >> 2;         // warp col tile (64 cols)
    const int gid = lane >> 2, tig = lane & 3;

    const __half* Pbase = g_P  + (size_t)(b * N_ + m0) * KTOT;
    const __half* Vbase = g_Vt + (size_t)(b * O_ + n0) * KTOT;

    const int lrow = tid >> 3;       // 0..31
    const int lseg = tid & 7;        // 0..7 (16B segment within 128B row-chunk)

    float acc[2][8][4];
#pragma unroll
    for (int mt = 0; mt < 2; mt++)
#pragma unroll
        for (int nh = 0; nh < 8; nh++)
#pragma unroll
            for (int r = 0; r < 4; r++) acc[mt][nh][r] = 0.f;

    // ldmatrix source addresses (lane-dependent), as smem byte offsets
    const uint32_t smem_base = smem_u32(hsm);
    // A: row = (l&15), coloff halves = (l>>4)*8
    const uint32_t a_lrow = lane & 15, a_lcol = (lane >> 4) * 8;
    // B: row = (l&7) + ((l>>4)<<3), coloff halves = ((l>>3)&1)*8
    const uint32_t b_lrow = (lane & 7) + ((lane >> 4) << 3), b_lcol = ((lane >> 3) & 1) * 8;

    // prefetch chunk 0
    uint4 pa[4], pb[4];
#pragma unroll
    for (int it = 0; it < 4; it++) {
        int row = lrow + it * 32;
        pa[it] = *(const uint4*)(Pbase + (size_t)row * KTOT + lseg * 8);
        pb[it] = *(const uint4*)(Vbase + (size_t)row * KTOT + lseg * 8);
    }

    for (int c = 0; c < 64; c++) {
        const int s = c & 1;
        __half* As = hsm + s * (2 * ABUF);
        __half* Bs = As + ABUF;
        // store prefetched chunk
#pragma unroll
        for (int it = 0; it < 4; it++) {
            int row = lrow + it * 32;
            *(uint4*)(As + row * STRD + lseg * 8) = pa[it];
            *(uint4*)(Bs + row * STRD + lseg * 8) = pb[it];
        }
        __syncthreads();

        // prefetch next chunk
        if (c < 63) {
#pragma unroll
            for (int it = 0; it < 4; it++) {
                int row = lrow + it * 32;
                pa[it] = *(const uint4*)(Pbase + (size_t)row * KTOT + (c + 1) * 64 + lseg * 8);
                pb[it] = *(const uint4*)(Vbase + (size_t)row * KTOT + (c + 1) * 64 + lseg * 8);
            }
        }

        const uint32_t As_b = smem_base + (uint32_t)(s * (2 * ABUF)) * 2;
        const uint32_t Bs_b = As_b + ABUF * 2;

#pragma unroll
        for (int ks = 0; ks < 4; ks++) {
            uint32_t af[2][4];
#pragma unroll
            for (int mt = 0; mt < 2; mt++) {
                uint32_t addr = As_b + ((wm * 32 + mt * 16 + a_lrow) * STRD + ks * 16 + a_lcol) * 2;
                LDSM_X4(af[mt][0], af[mt][1], af[mt][2], af[mt][3], addr);
            }
            uint32_t bf[4][4];
#pragma unroll
            for (int nt = 0; nt < 4; nt++) {
                uint32_t addr = Bs_b + ((wn * 64 + nt * 16 + b_lrow) * STRD + ks * 16 + b_lcol) * 2;
                LDSM_X4(bf[nt][0], bf[nt][1], bf[nt][2], bf[nt][3], addr);
            }
#pragma unroll
            for (int mt = 0; mt < 2; mt++)
#pragma unroll
                for (int nh = 0; nh < 8; nh++) {
                    const int nt = nh >> 1, hi = (nh & 1) * 2;
                    MMA16816(acc[mt][nh][0], acc[mt][nh][1], acc[mt][nh][2], acc[mt][nh][3],
                             af[mt][0], af[mt][1], af[mt][2], af[mt][3],
                             bf[nt][hi], bf[nt][hi + 1]);
                }
        }
        __syncthreads();
    }

    // epilogue: direct float2 stores
#pragma unroll
    for (int mt = 0; mt < 2; mt++) {
#pragma unroll
        for (int nh = 0; nh < 8; nh++) {
            int row = m0 + wm * 32 + mt * 16 + gid;
            int col = n0 + wn * 64 + nh * 8 + tig * 2;
            float2 v0 = make_float2(acc[mt][nh][0], acc[mt][nh][1]);
            float2 v1 = make_float2(acc[mt][nh][2], acc[mt][nh][3]);
            *(float2*)(out + ((size_t)(b * N_ + row)) * O_ + col) = v0;
            *(float2*)(out + ((size_t)(b * N_ + row + 8)) * O_ + col) = v1;
        }
    }
}

// ---------------- launch ----------------------------------------------------------
extern "C" void kernel_launch(void* const* d_in, const int* in_sizes, int n_in,
                              void* d_out, int out_size) {
    const float* x  = (const float*)d_in[0];
    const int*   AU = (const int*)d_in[1];
    const int*   AD = (const int*)d_in[2];
    const int*   AR = (const int*)d_in[3];
    const int*   AL = (const int*)d_in[4];
    const float* W  = (const float*)d_in[5];
    const float* a  = (const float*)d_in[6];
    float* out = (float*)d_out;

    cudaFuncSetAttribute(maintc_kernel, cudaFuncAttributeMaxDynamicSharedMemorySize, HSM_TOTAL);

    prep_kernel<<<D_, 256>>>(W, a);
    bits_kernel<<<(N_ * N_) / 256, 256>>>(AU, AD, AR, AL);
    gemm_whsum_kernel<<<dim3(ROWS / 64, O_ / 64, D_), 256>>>(x);
    evec_kernel<<<ROWS / 8, 256>>>(x);
    pbuild_kernel<<<ROWS, 256>>>();
    maintc_kernel<<<dim3(N_ / 128, O_ / 128, B_), 256, HSM_TOTAL>>>(out);
}

// round 5
// speedup vs baseline: 5.7398x; 1.4425x over previous
#include <cuda_runtime.h>
#include <cuda_fp16.h>
#include <math.h>
#include <stdint.h>

// Problem constants
#define B_   8
#define N_   1024
#define F_   256
#define O_   256
#define H_   2
#define D_   4
#define ROWS (B_ * N_)       // 8192
#define KTOT 4096            // D_ * N_

// ---------------- scratch ---------------------------------------------------------
__device__ float   g_vsrc[D_ * F_];
__device__ float   g_vdst[D_ * F_];
__device__ float   g_esrc[D_ * B_ * N_];
__device__ float   g_edst[D_ * B_ * N_];
__device__ uint8_t g_bits[N_ * N_];
__device__ __half  g_Xh [ROWS * F_];            // fp16 X, 4 MB
__device__ __half  g_Wth[D_ * O_ * F_];         // [(d*256+o)][f] fp16, 0.5 MB
__device__ __half  g_P [ROWS * KTOT];           // [b*N+i][d*N+j]  67 MB
__device__ __half  g_Vt[B_ * O_ * KTOT];        // [b*O+o][d*N+j]  17 MB

__device__ __forceinline__ uint32_t smem_u32(const void* p) {
    uint32_t a;
    asm("{ .reg .u64 t; cvta.to.shared.u64 t, %1; cvt.u32.u64 %0, t; }" : "=r"(a) : "l"(p));
    return a;
}

#define LDSM_X4(r0, r1, r2, r3, addr) \
    asm volatile("ldmatrix.sync.aligned.m8n8.x4.shared.b16 {%0,%1,%2,%3}, [%4];" \
        : "=r"(r0), "=r"(r1), "=r"(r2), "=r"(r3) : "r"(addr))

#define MMA16816(c0, c1, c2, c3, a0, a1, a2, a3, b0, b1) \
    asm volatile("mma.sync.aligned.m16n8k16.row.col.f32.f16.f16.f32 " \
        "{%0,%1,%2,%3}, {%4,%5,%6,%7}, {%8,%9}, {%0,%1,%2,%3};" \
        : "+f"(c0), "+f"(c1), "+f"(c2), "+f"(c3) \
        : "r"(a0), "r"(a1), "r"(a2), "r"(a3), "r"(b0), "r"(b1))

// ---------------- prep: Wth fp16 transposed; vsrc/vdst ----------------------------
__global__ void prep_kernel(const float* __restrict__ W, const float* __restrict__ a) {
    int d = blockIdx.x;
    int tid = threadIdx.x;
    __shared__ float sa[2 * O_];
    for (int idx = tid; idx < 2 * O_; idx += blockDim.x)
        sa[idx] = a[(d * 2 + 1) * (2 * O_) + idx];
    __syncthreads();

    const float* W0 = W + (size_t)(d * 2 + 0) * F_ * O_;
    const float* W1 = W + (size_t)(d * 2 + 1) * F_ * O_;
    // Wth[(d*256+o)][f] = fp16(W0[f][o] + W1[f][o]); coalesced writes
    for (int idx = tid; idx < F_ * O_; idx += blockDim.x) {
        int o = idx >> 8, f = idx & 255;
        float w = W0[f * O_ + o] + W1[f * O_ + o];
        g_Wth[(size_t)d * F_ * O_ + idx] = __float2half_rn(w);
    }

    int f = tid;
    float s1 = 0.f, s2 = 0.f;
    const float* w1r = W1 + f * O_;
    for (int o = 0; o < O_; o++) {
        float w = w1r[o];
        s1 += w * sa[o];
        s2 += w * sa[O_ + o];
    }
    g_vsrc[d * F_ + f] = s1;
    g_vdst[d * F_ + f] = s2;
}

// ---------------- X -> fp16 -------------------------------------------------------
__global__ void xh_kernel(const float* __restrict__ X) {
    int idx = blockIdx.x * 256 + threadIdx.x;     // each handles 8 floats
    const float4* src = (const float4*)X + idx * 2;
    float4 v0 = src[0], v1 = src[1];
    __half2 h0 = __floats2half2_rn(v0.x, v0.y);
    __half2 h1 = __floats2half2_rn(v0.z, v0.w);
    __half2 h2 = __floats2half2_rn(v1.x, v1.y);
    __half2 h3 = __floats2half2_rn(v1.z, v1.w);
    uint4 pack;
    pack.x = *(uint32_t*)&h0; pack.y = *(uint32_t*)&h1;
    pack.z = *(uint32_t*)&h2; pack.w = *(uint32_t*)&h3;
    *((uint4*)g_Xh + idx) = pack;
}

// ---------------- bits ------------------------------------------------------------
__global__ void bits_kernel(const int* __restrict__ AU, const int* __restrict__ AD,
                            const int* __restrict__ AR, const int* __restrict__ AL) {
    int idx4 = blockIdx.x * 256 + threadIdx.x;    // 4 entries per thread
    int4 u = ((const int4*)AU)[idx4];
    int4 dd = ((const int4*)AD)[idx4];
    int4 r = ((const int4*)AR)[idx4];
    int4 l = ((const int4*)AL)[idx4];
    uint32_t pack = 0;
    pack |= ((u.x != 0) | ((dd.x != 0) << 1) | ((r.x != 0) << 2) | ((l.x != 0) << 3));
    pack |= ((u.y != 0) | ((dd.y != 0) << 1) | ((r.y != 0) << 2) | ((l.y != 0) << 3)) << 8;
    pack |= ((u.z != 0) | ((dd.z != 0) << 1) | ((r.z != 0) << 2) | ((l.z != 0) << 3)) << 16;
    pack |= ((u.w != 0) | ((dd.w != 0) << 1) | ((r.w != 0) << 2) | ((l.w != 0) << 3)) << 24;
    ((uint32_t*)g_bits)[idx4] = pack;
}

// ---------------- e_src / e_dst ---------------------------------------------------
__global__ void evec_kernel(const float* __restrict__ X) {
    int tid = threadIdx.x;
    int w = tid >> 5, lane = tid & 31;
    int row = blockIdx.x * 8 + w;
    if (row >= ROWS) return;
    int b = row >> 10, n = row & (N_ - 1);

    float xv[8];
#pragma unroll
    for (int t = 0; t < 8; t++) xv[t] = X[(size_t)row * F_ + lane + t * 32];

#pragma unroll
    for (int d = 0; d < D_; d++) {
        float s1 = 0.f, s2 = 0.f;
#pragma unroll
        for (int t = 0; t < 8; t++) {
            s1 += xv[t] * g_vsrc[d * F_ + lane + t * 32];
            s2 += xv[t] * g_vdst[d * F_ + lane + t * 32];
        }
#pragma unroll
        for (int off = 16; off > 0; off >>= 1) {
            s1 += __shfl_down_sync(0xffffffffu, s1, off);
            s2 += __shfl_down_sync(0xffffffffu, s2, off);
        }
        if (lane == 0) {
            g_esrc[(d * B_ + b) * N_ + n] = s1;
            g_edst[(d * B_ + b) * N_ + n] = s2;
        }
    }
}

// ---------------- P build: softmax row -> fp16 P ----------------------------------
__global__ void __launch_bounds__(256) pbuild_kernel() {
    const int row = blockIdx.x;            // b*N + i
    const int b = row >> 10, i = row & (N_ - 1);
    const int tid = threadIdx.x;
    const int wid = tid >> 5, lane = tid & 31;
    const int j0 = tid * 4;

    __shared__ float red[8];
    __shared__ float bc[2];

    uint32_t bw = ((const uint32_t*)(g_bits + (size_t)i * N_))[tid];

    float es0 = g_esrc[(0 * B_ + b) * N_ + i];
    float es1 = g_esrc[(1 * B_ + b) * N_ + i];
    float es2 = g_esrc[(2 * B_ + b) * N_ + i];
    float es3 = g_esrc[(3 * B_ + b) * N_ + i];

    float4 ed0 = *(const float4*)(g_edst + (0 * B_ + b) * N_ + j0);
    float4 ed1 = *(const float4*)(g_edst + (1 * B_ + b) * N_ + j0);
    float4 ed2 = *(const float4*)(g_edst + (2 * B_ + b) * N_ + j0);
    float4 ed3 = *(const float4*)(g_edst + (3 * B_ + b) * N_ + j0);

    float e[4];
    unsigned byt[4];
#pragma unroll
    for (int q = 0; q < 4; q++) {
        unsigned bb8 = (bw >> (q * 8)) & 0xFF;
        byt[q] = bb8;
        float ev = -INFINITY;
        if (bb8) {
            int ds = 31 - __clz(bb8);
            float e0q = (q == 0) ? ed0.x : (q == 1) ? ed0.y : (q == 2) ? ed0.z : ed0.w;
            float e1q = (q == 0) ? ed1.x : (q == 1) ? ed1.y : (q == 2) ? ed1.z : ed1.w;
            float e2q = (q == 0) ? ed2.x : (q == 1) ? ed2.y : (q == 2) ? ed2.z : ed2.w;
            float e3q = (q == 0) ? ed3.x : (q == 1) ? ed3.y : (q == 2) ? ed3.z : ed3.w;
            float edv = (ds == 0) ? e0q : (ds == 1) ? e1q : (ds == 2) ? e2q : e3q;
            float esv = (ds == 0) ? es0 : (ds == 1) ? es1 : (ds == 2) ? es2 : es3;
            float s = esv + edv;
            ev = s > 0.f ? s : 0.01f * s;
        }
        e[q] = ev;
    }

    float m = fmaxf(fmaxf(e[0], e[1]), fmaxf(e[2], e[3]));
#pragma unroll
    for (int off = 16; off > 0; off >>= 1)
        m = fmaxf(m, __shfl_xor_sync(0xffffffffu, m, off));
    if (lane == 0) red[wid] = m;
    __syncthreads();
    if (tid == 0) {
        float mm = red[0];
#pragma unroll
        for (int k = 1; k < 8; k++) mm = fmaxf(mm, red[k]);
        bc[0] = mm;
    }
    __syncthreads();
    float rmax = bc[0];

    float wv[4], psum = 0.f;
#pragma unroll
    for (int q = 0; q < 4; q++) {
        wv[q] = __expf(e[q] - rmax);
        psum += wv[q];
    }
#pragma unroll
    for (int off = 16; off > 0; off >>= 1)
        psum += __shfl_xor_sync(0xffffffffu, psum, off);
    if (lane == 0) red[wid] = psum;
    __syncthreads();
    if (tid == 0) {
        float ss = 0.f;
#pragma unroll
        for (int k = 0; k < 8; k++) ss += red[k];
        bc[1] = 1.0f / (ss * (float)H_);
    }
    __syncthreads();
    float inv = bc[1];

    __half* Prow = g_P + (size_t)row * KTOT;
#pragma unroll
    for (int d = 0; d < D_; d++) {
        uint64_t pack = 0;
#pragma unroll
        for (int q = 0; q < 4; q++) {
            float v = (byt[q] >> d) & 1 ? wv[q] * inv : 0.f;
            pack |= (uint64_t)__half_as_ushort(__float2half_rn(v)) << (q * 16);
        }
        *(uint64_t*)(Prow + d * N_ + j0) = pack;
    }
}

// ---------------- shared HMMA tiling constants ------------------------------------
#define STRD 72
#define ABUF (128 * STRD)                 // halves per matrix buffer
#define HSM_TOTAL (4 * ABUF * 2)          // bytes: 2 bufs x (A+B)

// ---------------- HMMA GEMM: Vt = fp16( Xh @ Wth^T ), M=8192 N=1024 K=256 ---------
__global__ void __launch_bounds__(256, 1) gemm_whsum_kernel() {
    extern __shared__ __align__(16) __half hsm[];
    const int tid = threadIdx.x;
    const int wid = tid >> 5, lane = tid & 31;
    const int m0 = blockIdx.x * 128;      // global m = b*N + j
    const int n0 = blockIdx.y * 128;      // n = d*256 + o

    const int wm = wid & 3, wn = wid >> 2;
    const int gid = lane >> 2, tig = lane & 3;

    const __half* Abase = g_Xh  + (size_t)m0 * F_;
    const __half* Bbase = g_Wth + (size_t)n0 * F_;

    const int lrow = tid >> 3, lseg = tid & 7;

    float acc[2][8][4];
#pragma unroll
    for (int mt = 0; mt < 2; mt++)
#pragma unroll
        for (int nh = 0; nh < 8; nh++)
#pragma unroll
            for (int r = 0; r < 4; r++) acc[mt][nh][r] = 0.f;

    const uint32_t smem_base = smem_u32(hsm);
    const uint32_t a_lrow = lane & 15, a_lcol = (lane >> 4) * 8;
    const uint32_t b_lrow = (lane & 7) + ((lane >> 4) << 3), b_lcol = ((lane >> 3) & 1) * 8;

    uint4 pa[4], pb[4];
#pragma unroll
    for (int it = 0; it < 4; it++) {
        int row = lrow + it * 32;
        pa[it] = *(const uint4*)(Abase + (size_t)row * F_ + lseg * 8);
        pb[it] = *(const uint4*)(Bbase + (size_t)row * F_ + lseg * 8);
    }

    for (int c = 0; c < 4; c++) {
        const int s = c & 1;
        __half* As = hsm + s * (2 * ABUF);
        __half* Bs = As + ABUF;
#pragma unroll
        for (int it = 0; it < 4; it++) {
            int row = lrow + it * 32;
            *(uint4*)(As + row * STRD + lseg * 8) = pa[it];
            *(uint4*)(Bs + row * STRD + lseg * 8) = pb[it];
        }
        __syncthreads();

        if (c < 3) {
#pragma unroll
            for (int it = 0; it < 4; it++) {
                int row = lrow + it * 32;
                pa[it] = *(const uint4*)(Abase + (size_t)row * F_ + (c + 1) * 64 + lseg * 8);
                pb[it] = *(const uint4*)(Bbase + (size_t)row * F_ + (c + 1) * 64 + lseg * 8);
            }
        }

        const uint32_t As_b = smem_base + (uint32_t)(s * (2 * ABUF)) * 2;
        const uint32_t Bs_b = As_b + ABUF * 2;

#pragma unroll
        for (int ks = 0; ks < 4; ks++) {
            uint32_t af[2][4];
#pragma unroll
            for (int mt = 0; mt < 2; mt++) {
                uint32_t addr = As_b + ((wm * 32 + mt * 16 + a_lrow) * STRD + ks * 16 + a_lcol) * 2;
                LDSM_X4(af[mt][0], af[mt][1], af[mt][2], af[mt][3], addr);
            }
            uint32_t bf[4][4];
#pragma unroll
            for (int nt = 0; nt < 4; nt++) {
                uint32_t addr = Bs_b + ((wn * 64 + nt * 16 + b_lrow) * STRD + ks * 16 + b_lcol) * 2;
                LDSM_X4(bf[nt][0], bf[nt][1], bf[nt][2], bf[nt][3], addr);
            }
#pragma unroll
            for (int mt = 0; mt < 2; mt++)
#pragma unroll
                for (int nh = 0; nh < 8; nh++) {
                    const int nt = nh >> 1, hi = (nh & 1) * 2;
                    MMA16816(acc[mt][nh][0], acc[mt][nh][1], acc[mt][nh][2], acc[mt][nh][3],
                             af[mt][0], af[mt][1], af[mt][2], af[mt][3],
                             bf[nt][hi], bf[nt][hi + 1]);
                }
        }
        __syncthreads();
    }

    // epilogue: transpose via smem -> coalesced Vt[(b*256+o)][d*1024+j]
    __half* til = hsm;   // [o_local][136] stride
#pragma unroll
    for (int mt = 0; mt < 2; mt++)
#pragma unroll
        for (int nh = 0; nh < 8; nh++) {
            int ml = wm * 32 + mt * 16 + gid;
            int cl = wn * 64 + nh * 8 + tig * 2;
            til[(cl + 0) * 136 + ml]     = __float2half_rn(acc[mt][nh][0]);
            til[(cl + 1) * 136 + ml]     = __float2half_rn(acc[mt][nh][1]);
            til[(cl + 0) * 136 + ml + 8] = __float2half_rn(acc[mt][nh][2]);
            til[(cl + 1) * 136 + ml + 8] = __float2half_rn(acc[mt][nh][3]);
        }
    __syncthreads();

    const int b  = m0 >> 10;
    const int j0 = m0 & (N_ - 1);
    const int d  = n0 >> 8;
    const int o0 = n0 & 255;
#pragma unroll
    for (int it = 0; it < 8; it++) {
        int q = tid * 8 + it;
        int ol = q >> 4, seg = q & 15;
        uint4 v = *(uint4*)(til + ol * 136 + seg * 8);
        *(uint4*)(g_Vt + (size_t)(b * O_ + o0 + ol) * KTOT + d * N_ + j0 + seg * 8) = v;
    }
}

// ---------------- main GEMM: out[b] = P[b] @ Vt[b]^T  via HMMA --------------------
__global__ void __launch_bounds__(256, 1) maintc_kernel(float* __restrict__ out) {
    extern __shared__ __align__(16) __half hsm[];
    const int tid = threadIdx.x;
    const int wid = tid >> 5, lane = tid & 31;
    const int m0 = blockIdx.x * 128;
    const int n0 = blockIdx.y * 128;
    const int b  = blockIdx.z;

    const int wm = wid & 3, wn = wid >> 2;
    const int gid = lane >> 2, tig = lane & 3;

    const __half* Pbase = g_P  + (size_t)(b * N_ + m0) * KTOT;
    const __half* Vbase = g_Vt + (size_t)(b * O_ + n0) * KTOT;

    const int lrow = tid >> 3, lseg = tid & 7;

    float acc[2][8][4];
#pragma unroll
    for (int mt = 0; mt < 2; mt++)
#pragma unroll
        for (int nh = 0; nh < 8; nh++)
#pragma unroll
            for (int r = 0; r < 4; r++) acc[mt][nh][r] = 0.f;

    const uint32_t smem_base = smem_u32(hsm);
    const uint32_t a_lrow = lane & 15, a_lcol = (lane >> 4) * 8;
    const uint32_t b_lrow = (lane & 7) + ((lane >> 4) << 3), b_lcol = ((lane >> 3) & 1) * 8;

    uint4 pa[4], pb[4];
#pragma unroll
    for (int it = 0; it < 4; it++) {
        int row = lrow + it * 32;
        pa[it] = *(const uint4*)(Pbase + (size_t)row * KTOT + lseg * 8);
        pb[it] = *(const uint4*)(Vbase + (size_t)row * KTOT + lseg * 8);
    }

    for (int c = 0; c < 64; c++) {
        const int s = c & 1;
        __half* As = hsm + s * (2 * ABUF);
        __half* Bs = As + ABUF;
#pragma unroll
        for (int it = 0; it < 4; it++) {
            int row = lrow + it * 32;
            *(uint4*)(As + row * STRD + lseg * 8) = pa[it];
            *(uint4*)(Bs + row * STRD + lseg * 8) = pb[it];
        }
        __syncthreads();

        if (c < 63) {
#pragma unroll
            for (int it = 0; it < 4; it++) {
                int row = lrow + it * 32;
                pa[it] = *(const uint4*)(Pbase + (size_t)row * KTOT + (c + 1) * 64 + lseg * 8);
                pb[it] = *(const uint4*)(Vbase + (size_t)row * KTOT + (c + 1) * 64 + lseg * 8);
            }
        }

        const uint32_t As_b = smem_base + (uint32_t)(s * (2 * ABUF)) * 2;
        const uint32_t Bs_b = As_b + ABUF * 2;

#pragma unroll
        for (int ks = 0; ks < 4; ks++) {
            uint32_t af[2][4];
#pragma unroll
            for (int mt = 0; mt < 2; mt++) {
                uint32_t addr = As_b + ((wm * 32 + mt * 16 + a_lrow) * STRD + ks * 16 + a_lcol) * 2;
                LDSM_X4(af[mt][0], af[mt][1], af[mt][2], af[mt][3], addr);
            }
            uint32_t bf[4][4];
#pragma unroll
            for (int nt = 0; nt < 4; nt++) {
                uint32_t addr = Bs_b + ((wn * 64 + nt * 16 + b_lrow) * STRD + ks * 16 + b_lcol) * 2;
                LDSM_X4(bf[nt][0], bf[nt][1], bf[nt][2], bf[nt][3], addr);
            }
#pragma unroll
            for (int mt = 0; mt < 2; mt++)
#pragma unroll
                for (int nh = 0; nh < 8; nh++) {
                    const int nt = nh >> 1, hi = (nh & 1) * 2;
                    MMA16816(acc[mt][nh][0], acc[mt][nh][1], acc[mt][nh][2], acc[mt][nh][3],
                             af[mt][0], af[mt][1], af[mt][2], af[mt][3],
                             bf[nt][hi], bf[nt][hi + 1]);
                }
        }
        __syncthreads();
    }

#pragma unroll
    for (int mt = 0; mt < 2; mt++) {
#pragma unroll
        for (int nh = 0; nh < 8; nh++) {
            int row = m0 + wm * 32 + mt * 16 + gid;
            int col = n0 + wn * 64 + nh * 8 + tig * 2;
            float2 v0 = make_float2(acc[mt][nh][0], acc[mt][nh][1]);
            float2 v1 = make_float2(acc[mt][nh][2], acc[mt][nh][3]);
            *(float2*)(out + ((size_t)(b * N_ + row)) * O_ + col) = v0;
            *(float2*)(out + ((size_t)(b * N_ + row + 8)) * O_ + col) = v1;
        }
    }
}

// ---------------- launch ----------------------------------------------------------
extern "C" void kernel_launch(void* const* d_in, const int* in_sizes, int n_in,
                              void* d_out, int out_size) {
    const float* x  = (const float*)d_in[0];
    const int*   AU = (const int*)d_in[1];
    const int*   AD = (const int*)d_in[2];
    const int*   AR = (const int*)d_in[3];
    const int*   AL = (const int*)d_in[4];
    const float* W  = (const float*)d_in[5];
    const float* a  = (const float*)d_in[6];
    float* out = (float*)d_out;

    cudaFuncSetAttribute(gemm_whsum_kernel, cudaFuncAttributeMaxDynamicSharedMemorySize, HSM_TOTAL);
    cudaFuncSetAttribute(maintc_kernel, cudaFuncAttributeMaxDynamicSharedMemorySize, HSM_TOTAL);

    // order chosen so the profiled launch (#6 with -s 5) is gemm_whsum
    prep_kernel<<<D_, 256>>>(W, a);
    bits_kernel<<<(N_ * N_ / 4) / 256, 256>>>(AU, AD, AR, AL);
    xh_kernel<<<(ROWS * F_ / 8) / 256, 256>>>(x);
    evec_kernel<<<ROWS / 8, 256>>>(x);
    pbuild_kernel<<<ROWS, 256>>>();
    gemm_whsum_kernel<<<dim3(ROWS / 128, 1024 / 128), 256, HSM_TOTAL>>>();
    maintc_kernel<<<dim3(N_ / 128, O_ / 128, B_), 256, HSM_TOTAL>>>(out);
}

// round 6
// speedup vs baseline: 5.8438x; 1.0181x over previous
#include <cuda_runtime.h>
#include <cuda_fp16.h>
#include <math.h>
#include <stdint.h>

// Problem constants
#define B_   8
#define N_   1024
#define F_   256
#define O_   256
#define H_   2
#define D_   4
#define ROWS (B_ * N_)       // 8192
#define KTOT 4096            // D_ * N_

// ---------------- scratch ---------------------------------------------------------
__device__ float   g_vsrc[D_ * F_];
__device__ float   g_vdst[D_ * F_];
__device__ float   g_esrc[D_ * B_ * N_];
__device__ float   g_edst[D_ * B_ * N_];
__device__ uint8_t g_bits[N_ * N_];
__device__ __half  g_Xh [ROWS * F_];            // fp16 X, 4 MB
__device__ __half  g_Wth[D_ * O_ * F_];         // [(d*256+o)][f] fp16
__device__ __half  g_P [ROWS * KTOT];           // [b*N+i][d*N+j]  67 MB
__device__ __half  g_Vt[B_ * O_ * KTOT];        // [b*O+o][d*N+j]  17 MB

__device__ __forceinline__ uint32_t smem_u32(const void* p) {
    uint32_t a;
    asm("{ .reg .u64 t; cvta.to.shared.u64 t, %1; cvt.u32.u64 %0, t; }" : "=r"(a) : "l"(p));
    return a;
}

#define LDSM_X4(r0, r1, r2, r3, addr) \
    asm volatile("ldmatrix.sync.aligned.m8n8.x4.shared.b16 {%0,%1,%2,%3}, [%4];" \
        : "=r"(r0), "=r"(r1), "=r"(r2), "=r"(r3) : "r"(addr))

#define MMA16816(c0, c1, c2, c3, a0, a1, a2, a3, b0, b1) \
    asm volatile("mma.sync.aligned.m16n8k16.row.col.f32.f16.f16.f32 " \
        "{%0,%1,%2,%3}, {%4,%5,%6,%7}, {%8,%9}, {%0,%1,%2,%3};" \
        : "+f"(c0), "+f"(c1), "+f"(c2), "+f"(c3) \
        : "r"(a0), "r"(a1), "r"(a2), "r"(a3), "r"(b0), "r"(b1))

__device__ __forceinline__ void cp16(uint32_t dst, const void* src) {
    asm volatile("cp.async.cg.shared.global [%0], [%1], 16;" :: "r"(dst), "l"(src));
}
#define CP_COMMIT() asm volatile("cp.async.commit_group;" ::: "memory")
#define CP_WAIT2()  asm volatile("cp.async.wait_group 2;" ::: "memory")

// ---------------- prep: Wth fp16 transposed; vsrc/vdst ----------------------------
__global__ void prep_kernel(const float* __restrict__ W, const float* __restrict__ a) {
    int d = blockIdx.x;
    int tid = threadIdx.x;
    __shared__ float sa[2 * O_];
    for (int idx = tid; idx < 2 * O_; idx += blockDim.x)
        sa[idx] = a[(d * 2 + 1) * (2 * O_) + idx];
    __syncthreads();

    const float* W0 = W + (size_t)(d * 2 + 0) * F_ * O_;
    const float* W1 = W + (size_t)(d * 2 + 1) * F_ * O_;
    for (int idx = tid; idx < F_ * O_; idx += blockDim.x) {
        int o = idx >> 8, f = idx & 255;
        float w = W0[f * O_ + o] + W1[f * O_ + o];
        g_Wth[(size_t)d * F_ * O_ + idx] = __float2half_rn(w);
    }

    int f = tid;
    float s1 = 0.f, s2 = 0.f;
    const float* w1r = W1 + f * O_;
    for (int o = 0; o < O_; o++) {
        float w = w1r[o];
        s1 += w * sa[o];
        s2 += w * sa[O_ + o];
    }
    g_vsrc[d * F_ + f] = s1;
    g_vdst[d * F_ + f] = s2;
}

// ---------------- X -> fp16 -------------------------------------------------------
__global__ void xh_kernel(const float* __restrict__ X) {
    int idx = blockIdx.x * 256 + threadIdx.x;
    const float4* src = (const float4*)X + idx * 2;
    float4 v0 = src[0], v1 = src[1];
    __half2 h0 = __floats2half2_rn(v0.x, v0.y);
    __half2 h1 = __floats2half2_rn(v0.z, v0.w);
    __half2 h2 = __floats2half2_rn(v1.x, v1.y);
    __half2 h3 = __floats2half2_rn(v1.z, v1.w);
    uint4 pack;
    pack.x = *(uint32_t*)&h0; pack.y = *(uint32_t*)&h1;
    pack.z = *(uint32_t*)&h2; pack.w = *(uint32_t*)&h3;
    *((uint4*)g_Xh + idx) = pack;
}

// ---------------- bits ------------------------------------------------------------
__global__ void bits_kernel(const int* __restrict__ AU, const int* __restrict__ AD,
                            const int* __restrict__ AR, const int* __restrict__ AL) {
    int idx4 = blockIdx.x * 256 + threadIdx.x;
    int4 u = ((const int4*)AU)[idx4];
    int4 dd = ((const int4*)AD)[idx4];
    int4 r = ((const int4*)AR)[idx4];
    int4 l = ((const int4*)AL)[idx4];
    uint32_t pack = 0;
    pack |= ((u.x != 0) | ((dd.x != 0) << 1) | ((r.x != 0) << 2) | ((l.x != 0) << 3));
    pack |= ((u.y != 0) | ((dd.y != 0) << 1) | ((r.y != 0) << 2) | ((l.y != 0) << 3)) << 8;
    pack |= ((u.z != 0) | ((dd.z != 0) << 1) | ((r.z != 0) << 2) | ((l.z != 0) << 3)) << 16;
    pack |= ((u.w != 0) | ((dd.w != 0) << 1) | ((r.w != 0) << 2) | ((l.w != 0) << 3)) << 24;
    ((uint32_t*)g_bits)[idx4] = pack;
}

// ---------------- e_src / e_dst ---------------------------------------------------
__global__ void evec_kernel(const float* __restrict__ X) {
    int tid = threadIdx.x;
    int w = tid >> 5, lane = tid & 31;
    int row = blockIdx.x * 8 + w;
    if (row >= ROWS) return;
    int b = row >> 10, n = row & (N_ - 1);

    float xv[8];
#pragma unroll
    for (int t = 0; t < 8; t++) xv[t] = X[(size_t)row * F_ + lane + t * 32];

#pragma unroll
    for (int d = 0; d < D_; d++) {
        float s1 = 0.f, s2 = 0.f;
#pragma unroll
        for (int t = 0; t < 8; t++) {
            s1 += xv[t] * g_vsrc[d * F_ + lane + t * 32];
            s2 += xv[t] * g_vdst[d * F_ + lane + t * 32];
        }
#pragma unroll
        for (int off = 16; off > 0; off >>= 1) {
            s1 += __shfl_down_sync(0xffffffffu, s1, off);
            s2 += __shfl_down_sync(0xffffffffu, s2, off);
        }
        if (lane == 0) {
            g_esrc[(d * B_ + b) * N_ + n] = s1;
            g_edst[(d * B_ + b) * N_ + n] = s2;
        }
    }
}

// ---------------- P build: softmax row -> fp16 P ----------------------------------
__global__ void __launch_bounds__(256) pbuild_kernel() {
    const int row = blockIdx.x;            // b*N + i
    const int b = row >> 10, i = row & (N_ - 1);
    const int tid = threadIdx.x;
    const int wid = tid >> 5, lane = tid & 31;
    const int j0 = tid * 4;

    __shared__ float red[8];
    __shared__ float bc[2];

    uint32_t bw = ((const uint32_t*)(g_bits + (size_t)i * N_))[tid];

    float es0 = g_esrc[(0 * B_ + b) * N_ + i];
    float es1 = g_esrc[(1 * B_ + b) * N_ + i];
    float es2 = g_esrc[(2 * B_ + b) * N_ + i];
    float es3 = g_esrc[(3 * B_ + b) * N_ + i];

    float4 ed0 = *(const float4*)(g_edst + (0 * B_ + b) * N_ + j0);
    float4 ed1 = *(const float4*)(g_edst + (1 * B_ + b) * N_ + j0);
    float4 ed2 = *(const float4*)(g_edst + (2 * B_ + b) * N_ + j0);
    float4 ed3 = *(const float4*)(g_edst + (3 * B_ + b) * N_ + j0);

    float e[4];
    unsigned byt[4];
#pragma unroll
    for (int q = 0; q < 4; q++) {
        unsigned bb8 = (bw >> (q * 8)) & 0xFF;
        byt[q] = bb8;
        float ev = -INFINITY;
        if (bb8) {
            int ds = 31 - __clz(bb8);
            float e0q = (q == 0) ? ed0.x : (q == 1) ? ed0.y : (q == 2) ? ed0.z : ed0.w;
            float e1q = (q == 0) ? ed1.x : (q == 1) ? ed1.y : (q == 2) ? ed1.z : ed1.w;
            float e2q = (q == 0) ? ed2.x : (q == 1) ? ed2.y : (q == 2) ? ed2.z : ed2.w;
            float e3q = (q == 0) ? ed3.x : (q == 1) ? ed3.y : (q == 2) ? ed3.z : ed3.w;
            float edv = (ds == 0) ? e0q : (ds == 1) ? e1q : (ds == 2) ? e2q : e3q;
            float esv = (ds == 0) ? es0 : (ds == 1) ? es1 : (ds == 2) ? es2 : es3;
            float s = esv + edv;
            ev = s > 0.f ? s : 0.01f * s;
        }
        e[q] = ev;
    }

    float m = fmaxf(fmaxf(e[0], e[1]), fmaxf(e[2], e[3]));
#pragma unroll
    for (int off = 16; off > 0; off >>= 1)
        m = fmaxf(m, __shfl_xor_sync(0xffffffffu, m, off));
    if (lane == 0) red[wid] = m;
    __syncthreads();
    if (tid == 0) {
        float mm = red[0];
#pragma unroll
        for (int k = 1; k < 8; k++) mm = fmaxf(mm, red[k]);
        bc[0] = mm;
    }
    __syncthreads();
    float rmax = bc[0];

    float wv[4], psum = 0.f;
#pragma unroll
    for (int q = 0; q < 4; q++) {
        wv[q] = __expf(e[q] - rmax);
        psum += wv[q];
    }
#pragma unroll
    for (int off = 16; off > 0; off >>= 1)
        psum += __shfl_xor_sync(0xffffffffu, psum, off);
    if (lane == 0) red[wid] = psum;
    __syncthreads();
    if (tid == 0) {
        float ss = 0.f;
#pragma unroll
        for (int k = 0; k < 8; k++) ss += red[k];
        bc[1] = 1.0f / (ss * (float)H_);
    }
    __syncthreads();
    float inv = bc[1];

    __half* Prow = g_P + (size_t)row * KTOT;
#pragma unroll
    for (int d = 0; d < D_; d++) {
        uint64_t pack = 0;
#pragma unroll
        for (int q = 0; q < 4; q++) {
            float v = (byt[q] >> d) & 1 ? wv[q] * inv : 0.f;
            pack |= (uint64_t)__half_as_ushort(__float2half_rn(v)) << (q * 16);
        }
        *(uint64_t*)(Prow + d * N_ + j0) = pack;
    }
}

// ---------------- shared HMMA tiling constants ------------------------------------
#define STRD 72
#define ABUF (128 * STRD)                 // halves per matrix buffer
#define HSM_GEMM (4 * ABUF * 2)           // 2-stage double buffer (gemm_whsum)
#define NSTG 4
#define HSM_MAIN (NSTG * 2 * ABUF * 2)    // 4-stage cp.async (maintc), 147456 B

// ---------------- HMMA GEMM: Vt = fp16( Xh @ Wth^T ), M=8192 N=1024 K=256 ---------
__global__ void __launch_bounds__(256, 1) gemm_whsum_kernel() {
    extern __shared__ __align__(16) __half hsm[];
    const int tid = threadIdx.x;
    const int wid = tid >> 5, lane = tid & 31;
    const int m0 = blockIdx.x * 128;
    const int n0 = blockIdx.y * 128;

    const int wm = wid & 3, wn = wid >> 2;
    const int gid = lane >> 2, tig = lane & 3;

    const __half* Abase = g_Xh  + (size_t)m0 * F_;
    const __half* Bbase = g_Wth + (size_t)n0 * F_;

    const int lrow = tid >> 3, lseg = tid & 7;

    float acc[2][8][4];
#pragma unroll
    for (int mt = 0; mt < 2; mt++)
#pragma unroll
        for (int nh = 0; nh < 8; nh++)
#pragma unroll
            for (int r = 0; r < 4; r++) acc[mt][nh][r] = 0.f;

    const uint32_t smem_base = smem_u32(hsm);
    const uint32_t a_lrow = lane & 15, a_lcol = (lane >> 4) * 8;
    const uint32_t b_lrow = (lane & 7) + ((lane >> 4) << 3), b_lcol = ((lane >> 3) & 1) * 8;

    uint4 pa[4], pb[4];
#pragma unroll
    for (int it = 0; it < 4; it++) {
        int row = lrow + it * 32;
        pa[it] = *(const uint4*)(Abase + (size_t)row * F_ + lseg * 8);
        pb[it] = *(const uint4*)(Bbase + (size_t)row * F_ + lseg * 8);
    }

    for (int c = 0; c < 4; c++) {
        const int s = c & 1;
        __half* As = hsm + s * (2 * ABUF);
        __half* Bs = As + ABUF;
#pragma unroll
        for (int it = 0; it < 4; it++) {
            int row = lrow + it * 32;
            *(uint4*)(As + row * STRD + lseg * 8) = pa[it];
            *(uint4*)(Bs + row * STRD + lseg * 8) = pb[it];
        }
        __syncthreads();

        if (c < 3) {
#pragma unroll
            for (int it = 0; it < 4; it++) {
                int row = lrow + it * 32;
                pa[it] = *(const uint4*)(Abase + (size_t)row * F_ + (c + 1) * 64 + lseg * 8);
                pb[it] = *(const uint4*)(Bbase + (size_t)row * F_ + (c + 1) * 64 + lseg * 8);
            }
        }

        const uint32_t As_b = smem_base + (uint32_t)(s * (2 * ABUF)) * 2;
        const uint32_t Bs_b = As_b + ABUF * 2;

#pragma unroll
        for (int ks = 0; ks < 4; ks++) {
            uint32_t af[2][4];
#pragma unroll
            for (int mt = 0; mt < 2; mt++) {
                uint32_t addr = As_b + ((wm * 32 + mt * 16 + a_lrow) * STRD + ks * 16 + a_lcol) * 2;
                LDSM_X4(af[mt][0], af[mt][1], af[mt][2], af[mt][3], addr);
            }
            uint32_t bf[4][4];
#pragma unroll
            for (int nt = 0; nt < 4; nt++) {
                uint32_t addr = Bs_b + ((wn * 64 + nt * 16 + b_lrow) * STRD + ks * 16 + b_lcol) * 2;
                LDSM_X4(bf[nt][0], bf[nt][1], bf[nt][2], bf[nt][3], addr);
            }
#pragma unroll
            for (int mt = 0; mt < 2; mt++)
#pragma unroll
                for (int nh = 0; nh < 8; nh++) {
                    const int nt = nh >> 1, hi = (nh & 1) * 2;
                    MMA16816(acc[mt][nh][0], acc[mt][nh][1], acc[mt][nh][2], acc[mt][nh][3],
                             af[mt][0], af[mt][1], af[mt][2], af[mt][3],
                             bf[nt][hi], bf[nt][hi + 1]);
                }
        }
        __syncthreads();
    }

    // epilogue: transpose via smem -> coalesced Vt[(b*256+o)][d*1024+j]
    __half* til = hsm;
#pragma unroll
    for (int mt = 0; mt < 2; mt++)
#pragma unroll
        for (int nh = 0; nh < 8; nh++) {
            int ml = wm * 32 + mt * 16 + gid;
            int cl = wn * 64 + nh * 8 + tig * 2;
            til[(cl + 0) * 136 + ml]     = __float2half_rn(acc[mt][nh][0]);
            til[(cl + 1) * 136 + ml]     = __float2half_rn(acc[mt][nh][1]);
            til[(cl + 0) * 136 + ml + 8] = __float2half_rn(acc[mt][nh][2]);
            til[(cl + 1) * 136 + ml + 8] = __float2half_rn(acc[mt][nh][3]);
        }
    __syncthreads();

    const int b  = m0 >> 10;
    const int j0 = m0 & (N_ - 1);
    const int d  = n0 >> 8;
    const int o0 = n0 & 255;
#pragma unroll
    for (int it = 0; it < 8; it++) {
        int q = tid * 8 + it;
        int ol = q >> 4, seg = q & 15;
        uint4 v = *(uint4*)(til + ol * 136 + seg * 8);
        *(uint4*)(g_Vt + (size_t)(b * O_ + o0 + ol) * KTOT + d * N_ + j0 + seg * 8) = v;
    }
}

// ---------------- main GEMM: out[b] = P[b] @ Vt[b]^T, 4-stage cp.async ------------
__global__ void __launch_bounds__(256, 1) maintc_kernel(float* __restrict__ out) {
    extern __shared__ __align__(16) __half hsm[];
    const int tid = threadIdx.x;
    const int wid = tid >> 5, lane = tid & 31;
    const int m0 = blockIdx.x * 128;
    const int n0 = blockIdx.y * 128;
    const int b  = blockIdx.z;

    const int wm = wid & 3, wn = wid >> 2;
    const int gid = lane >> 2, tig = lane & 3;

    const __half* Pbase = g_P  + (size_t)(b * N_ + m0) * KTOT;
    const __half* Vbase = g_Vt + (size_t)(b * O_ + n0) * KTOT;

    const int lrow = tid >> 3, lseg = tid & 7;

    float acc[2][8][4];
#pragma unroll
    for (int mt = 0; mt < 2; mt++)
#pragma unroll
        for (int nh = 0; nh < 8; nh++)
#pragma unroll
            for (int r = 0; r < 4; r++) acc[mt][nh][r] = 0.f;

    const uint32_t smem_base = smem_u32(hsm);
    const uint32_t a_lrow = lane & 15, a_lcol = (lane >> 4) * 8;
    const uint32_t b_lrow = (lane & 7) + ((lane >> 4) << 3), b_lcol = ((lane >> 3) & 1) * 8;

    // issue chunks 0..2 into stages 0..2
#pragma unroll
    for (int ps = 0; ps < 3; ps++) {
        uint32_t As = smem_base + (uint32_t)(ps * (2 * ABUF)) * 2;
        uint32_t Bs = As + ABUF * 2;
#pragma unroll
        for (int it = 0; it < 4; it++) {
            int row = lrow + it * 32;
            uint32_t doff = (uint32_t)(row * STRD + lseg * 8) * 2;
            cp16(As + doff, Pbase + (size_t)row * KTOT + ps * 64 + lseg * 8);
            cp16(Bs + doff, Vbase + (size_t)row * KTOT + ps * 64 + lseg * 8);
        }
        CP_COMMIT();
    }

    for (int c = 0; c < 64; c++) {
        CP_WAIT2();
        __syncthreads();

        const int s = c & 3;
        const uint32_t As_b = smem_base + (uint32_t)(s * (2 * ABUF)) * 2;
        const uint32_t Bs_b = As_b + ABUF * 2;

        // issue chunk c+3 into stage (c+3)&3 == (c-1)&3 (freed by the barrier above)
        if (c < 61) {
            const int nc = c + 3;
            uint32_t As = smem_base + (uint32_t)((nc & 3) * (2 * ABUF)) * 2;
            uint32_t Bs = As + ABUF * 2;
#pragma unroll
            for (int it = 0; it < 4; it++) {
                int row = lrow + it * 32;
                uint32_t doff = (uint32_t)(row * STRD + lseg * 8) * 2;
                cp16(As + doff, Pbase + (size_t)row * KTOT + nc * 64 + lseg * 8);
                cp16(Bs + doff, Vbase + (size_t)row * KTOT + nc * 64 + lseg * 8);
            }
        }
        CP_COMMIT();

#pragma unroll
        for (int ks = 0; ks < 4; ks++) {
            uint32_t af[2][4];
#pragma unroll
            for (int mt = 0; mt < 2; mt++) {
                uint32_t addr = As_b + ((wm * 32 + mt * 16 + a_lrow) * STRD + ks * 16 + a_lcol) * 2;
                LDSM_X4(af[mt][0], af[mt][1], af[mt][2], af[mt][3], addr);
            }
            uint32_t bf[4][4];
#pragma unroll
            for (int nt = 0; nt < 4; nt++) {
                uint32_t addr = Bs_b + ((wn * 64 + nt * 16 + b_lrow) * STRD + ks * 16 + b_lcol) * 2;
                LDSM_X4(bf[nt][0], bf[nt][1], bf[nt][2], bf[nt][3], addr);
            }
#pragma unroll
            for (int mt = 0; mt < 2; mt++)
#pragma unroll
                for (int nh = 0; nh < 8; nh++) {
                    const int nt = nh >> 1, hi = (nh & 1) * 2;
                    MMA16816(acc[mt][nh][0], acc[mt][nh][1], acc[mt][nh][2], acc[mt][nh][3],
                             af[mt][0], af[mt][1], af[mt][2], af[mt][3],
                             bf[nt][hi], bf[nt][hi + 1]);
                }
        }
        __syncthreads();
    }

#pragma unroll
    for (int mt = 0; mt < 2; mt++) {
#pragma unroll
        for (int nh = 0; nh < 8; nh++) {
            int row = m0 + wm * 32 + mt * 16 + gid;
            int col = n0 + wn * 64 + nh * 8 + tig * 2;
            float2 v0 = make_float2(acc[mt][nh][0], acc[mt][nh][1]);
            float2 v1 = make_float2(acc[mt][nh][2], acc[mt][nh][3]);
            *(float2*)(out + ((size_t)(b * N_ + row)) * O_ + col) = v0;
            *(float2*)(out + ((size_t)(b * N_ + row + 8)) * O_ + col) = v1;
        }
    }
}

// ---------------- launch: fork/join graph -----------------------------------------
extern "C" void kernel_launch(void* const* d_in, const int* in_sizes, int n_in,
                              void* d_out, int out_size) {
    const float* x  = (const float*)d_in[0];
    const int*   AU = (const int*)d_in[1];
    const int*   AD = (const int*)d_in[2];
    const int*   AR = (const int*)d_in[3];
    const int*   AL = (const int*)d_in[4];
    const float* W  = (const float*)d_in[5];
    const float* a  = (const float*)d_in[6];
    float* out = (float*)d_out;

    static cudaStream_t s2 = 0;
    static cudaEvent_t evFork = 0, evJoin = 0;
    if (!s2) {
        cudaStreamCreateWithFlags(&s2, cudaStreamNonBlocking);
        cudaEventCreateWithFlags(&evFork, cudaEventDisableTiming);
        cudaEventCreateWithFlags(&evJoin, cudaEventDisableTiming);
        cudaFuncSetAttribute(gemm_whsum_kernel, cudaFuncAttributeMaxDynamicSharedMemorySize, HSM_GEMM);
        cudaFuncSetAttribute(maintc_kernel, cudaFuncAttributeMaxDynamicSharedMemorySize, HSM_MAIN);
    }

    // main stream: prep (both branches need it)
    prep_kernel<<<D_, 256>>>(W, a);
    cudaEventRecord(evFork, 0);

    // side stream: xh -> gemm_whsum  (produces Vt)
    cudaStreamWaitEvent(s2, evFork, 0);
    xh_kernel<<<(ROWS * F_ / 8) / 256, 256, 0, s2>>>(x);
    gemm_whsum_kernel<<<dim3(ROWS / 128, 1024 / 128), 256, HSM_GEMM, s2>>>();
    cudaEventRecord(evJoin, s2);

    // main stream: bits -> evec -> pbuild  (produces P)
    bits_kernel<<<(N_ * N_ / 4) / 256, 256>>>(AU, AD, AR, AL);
    evec_kernel<<<ROWS / 8, 256>>>(x);
    pbuild_kernel<<<ROWS, 256>>>();

    // join, then the big GEMM
    cudaStreamWaitEvent(0, evJoin, 0);
    maintc_kernel<<<dim3(N_ / 128, O_ / 128, B_), 256, HSM_MAIN>>>(out);
}

// round 7
// speedup vs baseline: 9.7933x; 1.6758x over previous
#include <cuda_runtime.h>
#include <cuda_fp16.h>
#include <math.h>
#include <stdint.h>

// Problem constants
#define B_   8
#define N_   1024
#define F_   256
#define O_   256
#define H_   2
#define D_   4
#define ROWS (B_ * N_)       // 8192
#define KTOT 4096            // D_ * N_

// ---------------- scratch ---------------------------------------------------------
__device__ float   g_vsrc[D_ * F_];
__device__ float   g_vdst[D_ * F_];
__device__ float   g_esrc[D_ * B_ * N_];
__device__ float   g_edst[D_ * B_ * N_];
__device__ uint8_t g_bits[N_ * N_];
__device__ __half  g_Xh [ROWS * F_];            // fp16 X, 4 MB
__device__ __half  g_Wth[D_ * O_ * F_];         // [(d*256+o)][f] fp16
__device__ __half  g_P [ROWS * KTOT];           // [b*N+i][d*N+j]  67 MB
__device__ __half  g_Vt[B_ * O_ * KTOT];        // [b*O+o][d*N+j]  17 MB

__device__ __forceinline__ uint32_t smem_u32(const void* p) {
    uint32_t a;
    asm("{ .reg .u64 t; cvta.to.shared.u64 t, %1; cvt.u32.u64 %0, t; }" : "=r"(a) : "l"(p));
    return a;
}

#define LDSM_X4(r0, r1, r2, r3, addr) \
    asm volatile("ldmatrix.sync.aligned.m8n8.x4.shared.b16 {%0,%1,%2,%3}, [%4];" \
        : "=r"(r0), "=r"(r1), "=r"(r2), "=r"(r3) : "r"(addr))

#define MMA16816(c0, c1, c2, c3, a0, a1, a2, a3, b0, b1) \
    asm volatile("mma.sync.aligned.m16n8k16.row.col.f32.f16.f16.f32 " \
        "{%0,%1,%2,%3}, {%4,%5,%6,%7}, {%8,%9}, {%0,%1,%2,%3};" \
        : "+f"(c0), "+f"(c1), "+f"(c2), "+f"(c3) \
        : "r"(a0), "r"(a1), "r"(a2), "r"(a3), "r"(b0), "r"(b1))

__device__ __forceinline__ void cp16(uint32_t dst, const void* src) {
    asm volatile("cp.async.cg.shared.global [%0], [%1], 16;" :: "r"(dst), "l"(src));
}
#define CP_COMMIT() asm volatile("cp.async.commit_group;" ::: "memory")
#define CP_WAIT2()  asm volatile("cp.async.wait_group 2;" ::: "memory")

// ---------------- prep2: coalesced Wth transpose-add + warp-GEMV vsrc/vdst --------
// grid (D_, 17): y<16 -> one 64x64 transpose tile; y==16 -> vsrc/vdst GEMV
__global__ void __launch_bounds__(256) prep2_kernel(const float* __restrict__ W,
                                                    const float* __restrict__ a) {
    const int d = blockIdx.x;
    const int task = blockIdx.y;
    const int tid = threadIdx.x;
    const float* W0 = W + (size_t)(d * 2 + 0) * F_ * O_;
    const float* W1 = W + (size_t)(d * 2 + 1) * F_ * O_;

    if (task < 16) {
        const int fr = (task >> 2) * 64, oc = (task & 3) * 64;
        __shared__ float t[64][65];
#pragma unroll
        for (int p = 0; p < 16; p++) {
            int idx = p * 256 + tid;
            int o = idx & 63, f = idx >> 6;            // coalesced over o
            t[f][o] = W0[(size_t)(fr + f) * O_ + oc + o] + W1[(size_t)(fr + f) * O_ + oc + o];
        }
        __syncthreads();
#pragma unroll
        for (int p = 0; p < 16; p++) {
            int idx = p * 256 + tid;
            int f = idx & 63, o = idx >> 6;            // coalesced over f
            g_Wth[(size_t)(d * O_ + oc + o) * F_ + fr + f] = __float2half_rn(t[f][o]);
        }
    } else {
        __shared__ float sa[2 * O_];
        for (int i = tid; i < 2 * O_; i += 256)
            sa[i] = a[(d * 2 + 1) * (2 * O_) + i];
        __syncthreads();
        const int w = tid >> 5, lane = tid & 31;
        const float4* a1v = (const float4*)sa;
        const float4* a2v = (const float4*)(sa + O_);
        for (int r = 0; r < 32; r++) {
            int f = w * 32 + r;
            const float4* row = (const float4*)(W1 + (size_t)f * O_);
            float s1 = 0.f, s2 = 0.f;
#pragma unroll
            for (int q = 0; q < 2; q++) {
                float4 v = row[lane + q * 32];
                float4 x1 = a1v[lane + q * 32];
                float4 x2 = a2v[lane + q * 32];
                s1 += v.x * x1.x + v.y * x1.y + v.z * x1.z + v.w * x1.w;
                s2 += v.x * x2.x + v.y * x2.y + v.z * x2.z + v.w * x2.w;
            }
#pragma unroll
            for (int off = 16; off > 0; off >>= 1) {
                s1 += __shfl_down_sync(0xffffffffu, s1, off);
                s2 += __shfl_down_sync(0xffffffffu, s2, off);
            }
            if (lane == 0) {
                g_vsrc[d * F_ + f] = s1;
                g_vdst[d * F_ + f] = s2;
            }
        }
    }
}

// ---------------- X -> fp16 -------------------------------------------------------
__global__ void xh_kernel(const float* __restrict__ X) {
    int idx = blockIdx.x * 256 + threadIdx.x;
    const float4* src = (const float4*)X + idx * 2;
    float4 v0 = src[0], v1 = src[1];
    __half2 h0 = __floats2half2_rn(v0.x, v0.y);
    __half2 h1 = __floats2half2_rn(v0.z, v0.w);
    __half2 h2 = __floats2half2_rn(v1.x, v1.y);
    __half2 h3 = __floats2half2_rn(v1.z, v1.w);
    uint4 pack;
    pack.x = *(uint32_t*)&h0; pack.y = *(uint32_t*)&h1;
    pack.z = *(uint32_t*)&h2; pack.w = *(uint32_t*)&h3;
    *((uint4*)g_Xh + idx) = pack;
}

// ---------------- e_src / e_dst + fused adjacency-bit packing ---------------------
__global__ void evec_kernel(const float* __restrict__ X,
                            const int* __restrict__ AU, const int* __restrict__ AD,
                            const int* __restrict__ AR, const int* __restrict__ AL) {
    int tid = threadIdx.x;

    // fused bits packing: exactly N*N/4 threads in this grid (1024 x 256)
    {
        int idx4 = blockIdx.x * 256 + tid;
        int4 u = ((const int4*)AU)[idx4];
        int4 dd = ((const int4*)AD)[idx4];
        int4 r = ((const int4*)AR)[idx4];
        int4 l = ((const int4*)AL)[idx4];
        uint32_t pack = 0;
        pack |= ((u.x != 0) | ((dd.x != 0) << 1) | ((r.x != 0) << 2) | ((l.x != 0) << 3));
        pack |= ((u.y != 0) | ((dd.y != 0) << 1) | ((r.y != 0) << 2) | ((l.y != 0) << 3)) << 8;
        pack |= ((u.z != 0) | ((dd.z != 0) << 1) | ((r.z != 0) << 2) | ((l.z != 0) << 3)) << 16;
        pack |= ((u.w != 0) | ((dd.w != 0) << 1) | ((r.w != 0) << 2) | ((l.w != 0) << 3)) << 24;
        ((uint32_t*)g_bits)[idx4] = pack;
    }

    int w = tid >> 5, lane = tid & 31;
    int row = blockIdx.x * 8 + w;
    int b = row >> 10, n = row & (N_ - 1);

    float xv[8];
#pragma unroll
    for (int t = 0; t < 8; t++) xv[t] = X[(size_t)row * F_ + lane + t * 32];

#pragma unroll
    for (int d = 0; d < D_; d++) {
        float s1 = 0.f, s2 = 0.f;
#pragma unroll
        for (int t = 0; t < 8; t++) {
            s1 += xv[t] * g_vsrc[d * F_ + lane + t * 32];
            s2 += xv[t] * g_vdst[d * F_ + lane + t * 32];
        }
#pragma unroll
        for (int off = 16; off > 0; off >>= 1) {
            s1 += __shfl_down_sync(0xffffffffu, s1, off);
            s2 += __shfl_down_sync(0xffffffffu, s2, off);
        }
        if (lane == 0) {
            g_esrc[(d * B_ + b) * N_ + n] = s1;
            g_edst[(d * B_ + b) * N_ + n] = s2;
        }
    }
}

// ---------------- P build: softmax row -> fp16 P ----------------------------------
__global__ void __launch_bounds__(256) pbuild_kernel() {
    const int row = blockIdx.x;            // b*N + i
    const int b = row >> 10, i = row & (N_ - 1);
    const int tid = threadIdx.x;
    const int wid = tid >> 5, lane = tid & 31;
    const int j0 = tid * 4;

    __shared__ float red[8];
    __shared__ float bc[2];

    uint32_t bw = ((const uint32_t*)(g_bits + (size_t)i * N_))[tid];

    float es0 = g_esrc[(0 * B_ + b) * N_ + i];
    float es1 = g_esrc[(1 * B_ + b) * N_ + i];
    float es2 = g_esrc[(2 * B_ + b) * N_ + i];
    float es3 = g_esrc[(3 * B_ + b) * N_ + i];

    float4 ed0 = *(const float4*)(g_edst + (0 * B_ + b) * N_ + j0);
    float4 ed1 = *(const float4*)(g_edst + (1 * B_ + b) * N_ + j0);
    float4 ed2 = *(const float4*)(g_edst + (2 * B_ + b) * N_ + j0);
    float4 ed3 = *(const float4*)(g_edst + (3 * B_ + b) * N_ + j0);

    float e[4];
    unsigned byt[4];
#pragma unroll
    for (int q = 0; q < 4; q++) {
        unsigned bb8 = (bw >> (q * 8)) & 0xFF;
        byt[q] = bb8;
        float ev = -INFINITY;
        if (bb8) {
            int ds = 31 - __clz(bb8);
            float e0q = (q == 0) ? ed0.x : (q == 1) ? ed0.y : (q == 2) ? ed0.z : ed0.w;
            float e1q = (q == 0) ? ed1.x : (q == 1) ? ed1.y : (q == 2) ? ed1.z : ed1.w;
            float e2q = (q == 0) ? ed2.x : (q == 1) ? ed2.y : (q == 2) ? ed2.z : ed2.w;
            float e3q = (q == 0) ? ed3.x : (q == 1) ? ed3.y : (q == 2) ? ed3.z : ed3.w;
            float edv = (ds == 0) ? e0q : (ds == 1) ? e1q : (ds == 2) ? e2q : e3q;
            float esv = (ds == 0) ? es0 : (ds == 1) ? es1 : (ds == 2) ? es2 : es3;
            float s = esv + edv;
            ev = s > 0.f ? s : 0.01f * s;
        }
        e[q] = ev;
    }

    float m = fmaxf(fmaxf(e[0], e[1]), fmaxf(e[2], e[3]));
#pragma unroll
    for (int off = 16; off > 0; off >>= 1)
        m = fmaxf(m, __shfl_xor_sync(0xffffffffu, m, off));
    if (lane == 0) red[wid] = m;
    __syncthreads();
    if (tid == 0) {
        float mm = red[0];
#pragma unroll
        for (int k = 1; k < 8; k++) mm = fmaxf(mm, red[k]);
        bc[0] = mm;
    }
    __syncthreads();
    float rmax = bc[0];

    float wv[4], psum = 0.f;
#pragma unroll
    for (int q = 0; q < 4; q++) {
        wv[q] = __expf(e[q] - rmax);
        psum += wv[q];
    }
#pragma unroll
    for (int off = 16; off > 0; off >>= 1)
        psum += __shfl_xor_sync(0xffffffffu, psum, off);
    if (lane == 0) red[wid] = psum;
    __syncthreads();
    if (tid == 0) {
        float ss = 0.f;
#pragma unroll
        for (int k = 0; k < 8; k++) ss += red[k];
        bc[1] = 1.0f / (ss * (float)H_);
    }
    __syncthreads();
    float inv = bc[1];

    __half* Prow = g_P + (size_t)row * KTOT;
#pragma unroll
    for (int d = 0; d < D_; d++) {
        uint64_t pack = 0;
#pragma unroll
        for (int q = 0; q < 4; q++) {
            float v = (byt[q] >> d) & 1 ? wv[q] * inv : 0.f;
            pack |= (uint64_t)__half_as_ushort(__float2half_rn(v)) << (q * 16);
        }
        *(uint64_t*)(Prow + d * N_ + j0) = pack;
    }
}

// ---------------- shared HMMA tiling constants ------------------------------------
#define STRD 72
#define ABUF (128 * STRD)                 // halves per matrix buffer
#define HSM_GEMM (4 * ABUF * 2)           // 2-stage double buffer (gemm_whsum)
#define NSTG 4
#define HSM_MAIN (NSTG * 2 * ABUF * 2)    // 4-stage cp.async (maintc), 147456 B

// ---------------- HMMA GEMM: Vt = fp16( Xh @ Wth^T ), M=8192 N=1024 K=256 ---------
__global__ void __launch_bounds__(256, 1) gemm_whsum_kernel() {
    extern __shared__ __align__(16) __half hsm[];
    const int tid = threadIdx.x;
    const int wid = tid >> 5, lane = tid & 31;
    const int m0 = blockIdx.x * 128;
    const int n0 = blockIdx.y * 128;

    const int wm = wid & 3, wn = wid >> 2;
    const int gid = lane >> 2, tig = lane & 3;

    const __half* Abase = g_Xh  + (size_t)m0 * F_;
    const __half* Bbase = g_Wth + (size_t)n0 * F_;

    const int lrow = tid >> 3, lseg = tid & 7;

    float acc[2][8][4];
#pragma unroll
    for (int mt = 0; mt < 2; mt++)
#pragma unroll
        for (int nh = 0; nh < 8; nh++)
#pragma unroll
            for (int r = 0; r < 4; r++) acc[mt][nh][r] = 0.f;

    const uint32_t smem_base = smem_u32(hsm);
    const uint32_t a_lrow = lane & 15, a_lcol = (lane >> 4) * 8;
    const uint32_t b_lrow = (lane & 7) + ((lane >> 4) << 3), b_lcol = ((lane >> 3) & 1) * 8;

    uint4 pa[4], pb[4];
#pragma unroll
    for (int it = 0; it < 4; it++) {
        int row = lrow + it * 32;
        pa[it] = *(const uint4*)(Abase + (size_t)row * F_ + lseg * 8);
        pb[it] = *(const uint4*)(Bbase + (size_t)row * F_ + lseg * 8);
    }

    for (int c = 0; c < 4; c++) {
        const int s = c & 1;
        __half* As = hsm + s * (2 * ABUF);
        __half* Bs = As + ABUF;
#pragma unroll
        for (int it = 0; it < 4; it++) {
            int row = lrow + it * 32;
            *(uint4*)(As + row * STRD + lseg * 8) = pa[it];
            *(uint4*)(Bs + row * STRD + lseg * 8) = pb[it];
        }
        __syncthreads();

        if (c < 3) {
#pragma unroll
            for (int it = 0; it < 4; it++) {
                int row = lrow + it * 32;
                pa[it] = *(const uint4*)(Abase + (size_t)row * F_ + (c + 1) * 64 + lseg * 8);
                pb[it] = *(const uint4*)(Bbase + (size_t)row * F_ + (c + 1) * 64 + lseg * 8);
            }
        }

        const uint32_t As_b = smem_base + (uint32_t)(s * (2 * ABUF)) * 2;
        const uint32_t Bs_b = As_b + ABUF * 2;

#pragma unroll
        for (int ks = 0; ks < 4; ks++) {
            uint32_t af[2][4];
#pragma unroll
            for (int mt = 0; mt < 2; mt++) {
                uint32_t addr = As_b + ((wm * 32 + mt * 16 + a_lrow) * STRD + ks * 16 + a_lcol) * 2;
                LDSM_X4(af[mt][0], af[mt][1], af[mt][2], af[mt][3], addr);
            }
            uint32_t bf[4][4];
#pragma unroll
            for (int nt = 0; nt < 4; nt++) {
                uint32_t addr = Bs_b + ((wn * 64 + nt * 16 + b_lrow) * STRD + ks * 16 + b_lcol) * 2;
                LDSM_X4(bf[nt][0], bf[nt][1], bf[nt][2], bf[nt][3], addr);
            }
#pragma unroll
            for (int mt = 0; mt < 2; mt++)
#pragma unroll
                for (int nh = 0; nh < 8; nh++) {
                    const int nt = nh >> 1, hi = (nh & 1) * 2;
                    MMA16816(acc[mt][nh][0], acc[mt][nh][1], acc[mt][nh][2], acc[mt][nh][3],
                             af[mt][0], af[mt][1], af[mt][2], af[mt][3],
                             bf[nt][hi], bf[nt][hi + 1]);
                }
        }
        __syncthreads();
    }

    // epilogue: transpose via smem -> coalesced Vt[(b*256+o)][d*1024+j]
    __half* til = hsm;
#pragma unroll
    for (int mt = 0; mt < 2; mt++)
#pragma unroll
        for (int nh = 0; nh < 8; nh++) {
            int ml = wm * 32 + mt * 16 + gid;
            int cl = wn * 64 + nh * 8 + tig * 2;
            til[(cl + 0) * 136 + ml]     = __float2half_rn(acc[mt][nh][0]);
            til[(cl + 1) * 136 + ml]     = __float2half_rn(acc[mt][nh][1]);
            til[(cl + 0) * 136 + ml + 8] = __float2half_rn(acc[mt][nh][2]);
            til[(cl + 1) * 136 + ml + 8] = __float2half_rn(acc[mt][nh][3]);
        }
    __syncthreads();

    const int b  = m0 >> 10;
    const int j0 = m0 & (N_ - 1);
    const int d  = n0 >> 8;
    const int o0 = n0 & 255;
#pragma unroll
    for (int it = 0; it < 8; it++) {
        int q = tid * 8 + it;
        int ol = q >> 4, seg = q & 15;
        uint4 v = *(uint4*)(til + ol * 136 + seg * 8);
        *(uint4*)(g_Vt + (size_t)(b * O_ + o0 + ol) * KTOT + d * N_ + j0 + seg * 8) = v;
    }
}

// ---------------- main GEMM: out[b] = P[b] @ Vt[b]^T, 4-stage cp.async ------------
__global__ void __launch_bounds__(256, 1) maintc_kernel(float* __restrict__ out) {
    extern __shared__ __align__(16) __half hsm[];
    const int tid = threadIdx.x;
    const int wid = tid >> 5, lane = tid & 31;
    const int m0 = blockIdx.x * 128;
    const int n0 = blockIdx.y * 128;
    const int b  = blockIdx.z;

    const int wm = wid & 3, wn = wid >> 2;
    const int gid = lane >> 2, tig = lane & 3;

    const __half* Pbase = g_P  + (size_t)(b * N_ + m0) * KTOT;
    const __half* Vbase = g_Vt + (size_t)(b * O_ + n0) * KTOT;

    const int lrow = tid >> 3, lseg = tid & 7;

    float acc[2][8][4];
#pragma unroll
    for (int mt = 0; mt < 2; mt++)
#pragma unroll
        for (int nh = 0; nh < 8; nh++)
#pragma unroll
            for (int r = 0; r < 4; r++) acc[mt][nh][r] = 0.f;

    const uint32_t smem_base = smem_u32(hsm);
    const uint32_t a_lrow = lane & 15, a_lcol = (lane >> 4) * 8;
    const uint32_t b_lrow = (lane & 7) + ((lane >> 4) << 3), b_lcol = ((lane >> 3) & 1) * 8;

#pragma unroll
    for (int ps = 0; ps < 3; ps++) {
        uint32_t As = smem_base + (uint32_t)(ps * (2 * ABUF)) * 2;
        uint32_t Bs = As + ABUF * 2;
#pragma unroll
        for (int it = 0; it < 4; it++) {
            int row = lrow + it * 32;
            uint32_t doff = (uint32_t)(row * STRD + lseg * 8) * 2;
            cp16(As + doff, Pbase + (size_t)row * KTOT + ps * 64 + lseg * 8);
            cp16(Bs + doff, Vbase + (size_t)row * KTOT + ps * 64 + lseg * 8);
        }
        CP_COMMIT();
    }

    for (int c = 0; c < 64; c++) {
        CP_WAIT2();
        __syncthreads();

        const int s = c & 3;
        const uint32_t As_b = smem_base + (uint32_t)(s * (2 * ABUF)) * 2;
        const uint32_t Bs_b = As_b + ABUF * 2;

        if (c < 61) {
            const int nc = c + 3;
            uint32_t As = smem_base + (uint32_t)((nc & 3) * (2 * ABUF)) * 2;
            uint32_t Bs = As + ABUF * 2;
#pragma unroll
            for (int it = 0; it < 4; it++) {
                int row = lrow + it * 32;
                uint32_t doff = (uint32_t)(row * STRD + lseg * 8) * 2;
                cp16(As + doff, Pbase + (size_t)row * KTOT + nc * 64 + lseg * 8);
                cp16(Bs + doff, Vbase + (size_t)row * KTOT + nc * 64 + lseg * 8);
            }
        }
        CP_COMMIT();

#pragma unroll
        for (int ks = 0; ks < 4; ks++) {
            uint32_t af[2][4];
#pragma unroll
            for (int mt = 0; mt < 2; mt++) {
                uint32_t addr = As_b + ((wm * 32 + mt * 16 + a_lrow) * STRD + ks * 16 + a_lcol) * 2;
                LDSM_X4(af[mt][0], af[mt][1], af[mt][2], af[mt][3], addr);
            }
            uint32_t bf[4][4];
#pragma unroll
            for (int nt = 0; nt < 4; nt++) {
                uint32_t addr = Bs_b + ((wn * 64 + nt * 16 + b_lrow) * STRD + ks * 16 + b_lcol) * 2;
                LDSM_X4(bf[nt][0], bf[nt][1], bf[nt][2], bf[nt][3], addr);
            }
#pragma unroll
            for (int mt = 0; mt < 2; mt++)
#pragma unroll
                for (int nh = 0; nh < 8; nh++) {
                    const int nt = nh >> 1, hi = (nh & 1) * 2;
                    MMA16816(acc[mt][nh][0], acc[mt][nh][1], acc[mt][nh][2], acc[mt][nh][3],
                             af[mt][0], af[mt][1], af[mt][2], af[mt][3],
                             bf[nt][hi], bf[nt][hi + 1]);
                }
        }
        __syncthreads();
    }

#pragma unroll
    for (int mt = 0; mt < 2; mt++) {
#pragma unroll
        for (int nh = 0; nh < 8; nh++) {
            int row = m0 + wm * 32 + mt * 16 + gid;
            int col = n0 + wn * 64 + nh * 8 + tig * 2;
            float2 v0 = make_float2(acc[mt][nh][0], acc[mt][nh][1]);
            float2 v1 = make_float2(acc[mt][nh][2], acc[mt][nh][3]);
            *(float2*)(out + ((size_t)(b * N_ + row)) * O_ + col) = v0;
            *(float2*)(out + ((size_t)(b * N_ + row + 8)) * O_ + col) = v1;
        }
    }
}

// ---------------- launch: fork/join graph -----------------------------------------
extern "C" void kernel_launch(void* const* d_in, const int* in_sizes, int n_in,
                              void* d_out, int out_size) {
    const float* x  = (const float*)d_in[0];
    const int*   AU = (const int*)d_in[1];
    const int*   AD = (const int*)d_in[2];
    const int*   AR = (const int*)d_in[3];
    const int*   AL = (const int*)d_in[4];
    const float* W  = (const float*)d_in[5];
    const float* a  = (const float*)d_in[6];
    float* out = (float*)d_out;

    static cudaStream_t s2 = 0;
    static cudaEvent_t evFork = 0, evJoin = 0;
    if (!s2) {
        cudaStreamCreateWithFlags(&s2, cudaStreamNonBlocking);
        cudaEventCreateWithFlags(&evFork, cudaEventDisableTiming);
        cudaEventCreateWithFlags(&evJoin, cudaEventDisableTiming);
        cudaFuncSetAttribute(gemm_whsum_kernel, cudaFuncAttributeMaxDynamicSharedMemorySize, HSM_GEMM);
        cudaFuncSetAttribute(maintc_kernel, cudaFuncAttributeMaxDynamicSharedMemorySize, HSM_MAIN);
    }

    // head: prep2 (both branches depend on it)
    prep2_kernel<<<dim3(D_, 17), 256>>>(W, a);
    cudaEventRecord(evFork, 0);

    // side stream: xh -> gemm_whsum  (produces Vt)
    cudaStreamWaitEvent(s2, evFork, 0);
    xh_kernel<<<(ROWS * F_ / 8) / 256, 256, 0, s2>>>(x);
    gemm_whsum_kernel<<<dim3(ROWS / 128, 1024 / 128), 256, HSM_GEMM, s2>>>();
    cudaEventRecord(evJoin, s2);

    // main stream: evec(+bits) -> pbuild  (produces P)
    evec_kernel<<<ROWS / 8, 256>>>(x, AU, AD, AR, AL);
    pbuild_kernel<<<ROWS, 256>>>();

    // join, then the big GEMM
    cudaStreamWaitEvent(0, evJoin, 0);
    maintc_kernel<<<dim3(N_ / 128, O_ / 128, B_), 256, HSM_MAIN>>>(out);
}